// round 8
// baseline (speedup 1.0000x reference)
#include <cuda_runtime.h>
#include <cuda_fp16.h>
#include <cstdint>

#define B_   4
#define C_   256
#define CK_  448
#define N_   4096
#define NEGV (-1e15f)

// ---------------- device scratch ----------------
__device__ __half g_Qh[(size_t)B_*N_*CK_];
__device__ __half g_Kh[(size_t)B_*N_*CK_];
__device__ __half g_VTh[(size_t)B_*2*C_*N_];   // [b][j][n], j=2c:v, 2c+1:v^2
__device__ float  g_S[(size_t)B_*N_*N_];       // [b][q][k]
__device__ __half g_P[(size_t)B_*N_*N_];       // [b][q][k]
__device__ float  g_l[B_*N_];
__device__ float  g_O[(size_t)B_*N_*2*C_];     // [b][q][j]
__device__ float  g_cmean[B_*C_], g_crstd[B_*C_];
// fp16 hi/lo splits of proj inputs
__device__ __half g_CKh[(size_t)B_*CK_*N_], g_CKl[(size_t)B_*CK_*N_];
__device__ __half g_SKh[(size_t)B_*CK_*N_], g_SKl[(size_t)B_*CK_*N_];
__device__ __half g_Wfh[CK_*CK_], g_Wfl[CK_*CK_];
__device__ __half g_Wgh[CK_*CK_], g_Wgl[CK_*CK_];

// ---------------- f32x2 helpers (proj V GEMM) ----------------
typedef unsigned long long u64v;
__device__ __forceinline__ u64v pk2(float x, float y){u64v r;asm("mov.b64 %0,{%1,%2};":"=l"(r):"f"(x),"f"(y));return r;}
__device__ __forceinline__ void upk2(u64v v,float&x,float&y){asm("mov.b64 {%0,%1},%2;":"=f"(x),"=f"(y):"l"(v));}
__device__ __forceinline__ u64v ffma2(u64v a,u64v b,u64v c){u64v d;asm("fma.rn.f32x2 %0,%1,%2,%3;":"=l"(d):"l"(a),"l"(b),"l"(c));return d;}

// ---------------- mma.sync / ldmatrix / cp.async ----------------
__device__ __forceinline__ uint32_t smem_to_u32(const void*p){
    uint32_t a;asm("{ .reg .u64 t; cvta.to.shared.u64 t, %1; cvt.u32.u64 %0, t; }":"=r"(a):"l"(p));return a;}
__device__ __forceinline__ void mma16816(float* c, const uint32_t* a, const uint32_t* b){
    asm volatile("mma.sync.aligned.m16n8k16.row.col.f32.f16.f16.f32 "
        "{%0,%1,%2,%3}, {%4,%5,%6,%7}, {%8,%9}, {%0,%1,%2,%3};"
        : "+f"(c[0]),"+f"(c[1]),"+f"(c[2]),"+f"(c[3])
        : "r"(a[0]),"r"(a[1]),"r"(a[2]),"r"(a[3]), "r"(b[0]),"r"(b[1]));
}
__device__ __forceinline__ void ldm4(uint32_t* r, uint32_t addr){
    asm volatile("ldmatrix.sync.aligned.m8n8.x4.shared.b16 {%0,%1,%2,%3}, [%4];"
        :"=r"(r[0]),"=r"(r[1]),"=r"(r[2]),"=r"(r[3]):"r"(addr));
}
__device__ __forceinline__ void ldm4t(uint32_t* r, uint32_t addr){
    asm volatile("ldmatrix.sync.aligned.m8n8.x4.trans.shared.b16 {%0,%1,%2,%3}, [%4];"
        :"=r"(r[0]),"=r"(r[1]),"=r"(r[2]),"=r"(r[3]):"r"(addr));
}
__device__ __forceinline__ void cp16(uint32_t dst, const void* src){
    asm volatile("cp.async.cg.shared.global [%0], [%1], 16;" :: "r"(dst), "l"(src));
}
#define CP_COMMIT() asm volatile("cp.async.commit_group;" ::: "memory")
#define CP_WAIT2()  asm volatile("cp.async.wait_group 2;" ::: "memory")
#define CP_WAIT1()  asm volatile("cp.async.wait_group 1;" ::: "memory")
#define CP_WAIT0()  asm volatile("cp.async.wait_group 0;" ::: "memory")

// ---------------- fast exp on fma pipe ----------------
__device__ __forceinline__ float fast_exp(float x){
    float t = fmaxf(x * 1.4426950408889634f, -126.0f);
    float fi = t + 12582912.0f;
    int i = __float_as_int(fi) - 0x4B400000;
    float f = t - (fi - 12582912.0f);
    float p = 1.5424236e-4f;
    p = fmaf(p,f,1.3333558e-3f); p = fmaf(p,f,9.6181291e-3f);
    p = fmaf(p,f,5.5504109e-2f); p = fmaf(p,f,2.4022651e-1f);
    p = fmaf(p,f,6.9314718e-1f); p = fmaf(p,f,1.0f);
    return __int_as_float(__float_as_int(p) + (i<<23));
}

// ---------------- kernel 0: fp32 -> fp16 hi/lo split ----------------
__global__ __launch_bounds__(256) void split_kernel(const float* __restrict__ src,
                                                    __half* __restrict__ h,
                                                    __half* __restrict__ l, int n4){
    int i = blockIdx.x*256 + threadIdx.x;
    if(i >= n4) return;
    float4 v = ((const float4*)src)[i];
    __align__(8) __half hh[4], hl[4];
    float vv[4]={v.x,v.y,v.z,v.w};
    #pragma unroll
    for(int j=0;j<4;j++){
        __half a=__float2half_rn(vv[j]);
        hh[j]=a; hl[j]=__float2half_rn(vv[j]-__half2float(a));
    }
    ((uint2*)h)[i]=*(uint2*)hh;
    ((uint2*)l)[i]=*(uint2*)hl;
}

// ---------------- kernel 1: content stats ----------------
__global__ __launch_bounds__(256) void stats_kernel(const float* __restrict__ content){
    int bc = blockIdx.x, tid = threadIdx.x;
    const float4* x = (const float4*)(content + (size_t)bc*N_);
    float s=0.f,q=0.f;
    for(int i=tid;i<N_/4;i+=256){float4 v=x[i];s+=v.x+v.y+v.z+v.w;q+=v.x*v.x+v.y*v.y+v.z*v.z+v.w*v.w;}
    #pragma unroll
    for(int o=16;o;o>>=1){s+=__shfl_xor_sync(~0u,s,o);q+=__shfl_xor_sync(~0u,q,o);}
    __shared__ float ss[8],qq[8];
    int w=tid>>5,l=tid&31;
    if(l==0){ss[w]=s;qq[w]=q;}
    __syncthreads();
    if(tid==0){
        float S=0,Q=0;
        #pragma unroll
        for(int i=0;i<8;i++){S+=ss[i];Q+=qq[i];}
        float mean=S/(float)N_;
        float var=(Q-(float)N_*mean*mean)/(float)(N_-1);
        g_cmean[bc]=mean; g_crstd[bc]=rsqrtf(var+1e-5f);
    }
}

// ---------------- kernel 2a: HMMA projection for Q/K ----------------
// Y[b][n][448] = sum_c X[b][c][n] * W[o][c] + bias[o], 3-term hi/lo.
// CTA 128n x 64o, 8 warps (4n x 2o), chunk 64 c (7 chunks), 2 stages.
#define PM_XH 0
#define PM_XL 17408
#define PM_WH 34816
#define PM_WL 44032
#define PM_STAGE 53248
#define PM_SMEM (2*PM_STAGE)
__global__ __launch_bounds__(256) void proj_mma_kernel(const __half* __restrict__ Xh,
                                                       const __half* __restrict__ Xl,
                                                       const __half* __restrict__ Wh,
                                                       const __half* __restrict__ Wl,
                                                       const float* __restrict__ bias,
                                                       __half* __restrict__ Y){
    extern __shared__ char sm[];
    uint32_t sb = smem_to_u32(sm);
    int tid=threadIdx.x, lane=tid&31, wid=tid>>5;
    int g=lane>>2, tig=lane&3;
    int wn=(wid&3)*32, wo=(wid>>2)*32;
    int l8=lane&7, sel=lane>>3;
    int b=blockIdx.z, n0=blockIdx.x*128, o0=blockIdx.y*64;
    const __half* Xhg = Xh + (size_t)b*CK_*N_;
    const __half* Xlg = Xl + (size_t)b*CK_*N_;

    auto issue=[&](int ch, int st){
        uint32_t base = sb + st*PM_STAGE;
        int ck0=ch*64;
        for(int i=tid;i<1024;i+=256){
            int r=i>>4, s=i&15;
            size_t gi=(size_t)(ck0+r)*N_+n0+s*8;
            cp16(base+PM_XH + r*272 + s*16, Xhg + gi);
            cp16(base+PM_XL + r*272 + s*16, Xlg + gi);
        }
        for(int i=tid;i<512;i+=256){
            int r=i>>3, s=i&7;
            size_t gi=(size_t)(o0+r)*CK_+ck0+s*8;
            cp16(base+PM_WH + r*144 + s*16, Wh + gi);
            cp16(base+PM_WL + r*144 + s*16, Wl + gi);
        }
    };

    float acc[2][4][4];
    #pragma unroll
    for(int mi=0;mi<2;mi++)
        #pragma unroll
        for(int ni=0;ni<4;ni++)
            #pragma unroll
            for(int e=0;e<4;e++) acc[mi][ni][e]=0.f;

    // per-lane constant parts of the trans-A address
    int arow = (((sel&2)?8:0) + l8)*272;
    int acol = ((sel&1)?8:0)*2;
    int lrow = lane&15, lcol = lane>>4;

    issue(0,0); CP_COMMIT();
    for(int ch=0; ch<7; ch++){
        if(ch+1<7){ issue(ch+1,(ch+1)&1); CP_COMMIT(); CP_WAIT1(); } else { CP_WAIT0(); }
        __syncthreads();
        uint32_t stg = sb + (ch&1)*PM_STAGE;
        #pragma unroll
        for(int ks=0;ks<4;ks++){
            int kb=ks*16;
            uint32_t ah[2][4], al[2][4];
            #pragma unroll
            for(int mi=0;mi<2;mi++){
                uint32_t off = kb*272 + arow + (wn+mi*16)*2 + acol;
                ldm4t(ah[mi], stg+PM_XH + off);
                ldm4t(al[mi], stg+PM_XL + off);
            }
            uint32_t bh[4][2], bl[4][2];
            #pragma unroll
            for(int nb=0;nb<2;nb++){
                uint32_t r4[4];
                uint32_t off = (wo+nb*16+lrow)*144 + (kb+lcol*8)*2;
                ldm4(r4, stg+PM_WH + off);
                bh[2*nb][0]=r4[0]; bh[2*nb+1][0]=r4[1]; bh[2*nb][1]=r4[2]; bh[2*nb+1][1]=r4[3];
                ldm4(r4, stg+PM_WL + off);
                bl[2*nb][0]=r4[0]; bl[2*nb+1][0]=r4[1]; bl[2*nb][1]=r4[2]; bl[2*nb+1][1]=r4[3];
            }
            #pragma unroll
            for(int mi=0;mi<2;mi++)
                #pragma unroll
                for(int ni=0;ni<4;ni++){
                    mma16816(acc[mi][ni], ah[mi], bh[ni]);
                    mma16816(acc[mi][ni], ah[mi], bl[ni]);
                    mma16816(acc[mi][ni], al[mi], bh[ni]);
                }
        }
        __syncthreads();
    }
    // epilogue: add bias, round to fp16, store [b][n][CK_]
    #pragma unroll
    for(int mi=0;mi<2;mi++){
        int qr=wn+mi*16+g;
        #pragma unroll
        for(int ni=0;ni<4;ni++){
            int oc=wo+ni*8+tig*2;
            float2 bia=*(const float2*)&bias[o0+oc];
            __half2 h0=__floats2half2_rn(acc[mi][ni][0]+bia.x, acc[mi][ni][1]+bia.y);
            __half2 h1=__floats2half2_rn(acc[mi][ni][2]+bia.x, acc[mi][ni][3]+bia.y);
            *(__half2*)&Y[((size_t)(b*N_)+n0+qr)*CK_ + o0+oc]   = h0;
            *(__half2*)&Y[((size_t)(b*N_)+n0+qr+8)*CK_ + o0+oc] = h1;
        }
    }
}

// ---------------- kernel 2b: SIMT projection for V (v, v^2, transposed out) ----------------
template<int CIN>
__global__ __launch_bounds__(256) void projv_kernel(const float* __restrict__ X,
                                                    const float* __restrict__ W,
                                                    const float* __restrict__ bias,
                                                    __half* __restrict__ Yh){
    __shared__ float Xs[32*128];
    __shared__ float Ws[32*64];
    int b=blockIdx.z, n0=blockIdx.x*128, o0=blockIdx.y*64;
    int tid=threadIdx.x, tx=tid&15, ty=tid>>4;
    u64v acc2[4][4];
    #pragma unroll
    for(int p=0;p<4;p++)
        #pragma unroll
        for(int j=0;j<4;j++) acc2[p][j]=0ull;
    for(int c0=0;c0<CIN;c0+=32){
        __syncthreads();
        for(int e=tid;e<1024;e+=256){
            int cc=e>>5, nn=(e&31)<<2;
            *(float4*)&Xs[cc*128+nn]=*(const float4*)&X[((size_t)(b*CIN+c0+cc))*N_+n0+nn];
        }
        for(int e=tid;e<512;e+=256){
            int oo=e>>3, c4=(e&7)<<2;
            float4 v=*(const float4*)&W[(size_t)(o0+oo)*CIN+c0+c4];
            Ws[(c4+0)*64+oo]=v.x; Ws[(c4+1)*64+oo]=v.y; Ws[(c4+2)*64+oo]=v.z; Ws[(c4+3)*64+oo]=v.w;
        }
        __syncthreads();
        #pragma unroll 4
        for(int cc=0;cc<32;cc++){
            const u64v* xr=(const u64v*)&Xs[cc*128+ty*8];
            u64v x0=xr[0], x1=xr[1], x2=xr[2], x3=xr[3];
            float4 w4=*(const float4*)&Ws[cc*64+tx*4];
            u64v w0=pk2(w4.x,w4.x),w1=pk2(w4.y,w4.y),w2=pk2(w4.z,w4.z),w3=pk2(w4.w,w4.w);
            acc2[0][0]=ffma2(x0,w0,acc2[0][0]); acc2[0][1]=ffma2(x0,w1,acc2[0][1]);
            acc2[0][2]=ffma2(x0,w2,acc2[0][2]); acc2[0][3]=ffma2(x0,w3,acc2[0][3]);
            acc2[1][0]=ffma2(x1,w0,acc2[1][0]); acc2[1][1]=ffma2(x1,w1,acc2[1][1]);
            acc2[1][2]=ffma2(x1,w2,acc2[1][2]); acc2[1][3]=ffma2(x1,w3,acc2[1][3]);
            acc2[2][0]=ffma2(x2,w0,acc2[2][0]); acc2[2][1]=ffma2(x2,w1,acc2[2][1]);
            acc2[2][2]=ffma2(x2,w2,acc2[2][2]); acc2[2][3]=ffma2(x2,w3,acc2[2][3]);
            acc2[3][0]=ffma2(x3,w0,acc2[3][0]); acc2[3][1]=ffma2(x3,w1,acc2[3][1]);
            acc2[3][2]=ffma2(x3,w2,acc2[3][2]); acc2[3][3]=ffma2(x3,w3,acc2[3][3]);
        }
    }
    float a[8][4];
    #pragma unroll
    for(int p=0;p<4;p++)
        #pragma unroll
        for(int j=0;j<4;j++) upk2(acc2[p][j],a[2*p][j],a[2*p+1][j]);
    float4 bo=*(const float4*)&bias[o0+tx*4];
    float bb[4]={bo.x,bo.y,bo.z,bo.w};
    #pragma unroll
    for(int j=0;j<4;j++){
        __align__(16) __half vh[8], wh[8];
        #pragma unroll
        for(int i=0;i<8;i++){
            float y=a[i][j]+bb[j];
            vh[i]=__float2half_rn(y);
            wh[i]=__float2half_rn(y*y);
        }
        int o=o0+tx*4+j;
        size_t rv=((size_t)b*(2*C_)+2*o)*N_+n0+ty*8;
        *(uint4*)&Yh[rv]=*(uint4*)vh; *(uint4*)&Yh[rv+N_]=*(uint4*)wh;
    }
}

// ---------------- kernel 3: S = Q K^T  (mma.sync + ldmatrix, 1-term, 3-stage) ----------------
#define SG_Q  0
#define SG_KH 18432
#define SG_STAGE 55296
#define SG_SMEM (3*SG_STAGE)
__global__ __launch_bounds__(256) void sgemm_kernel(){
    extern __shared__ char sm[];
    uint32_t sb = smem_to_u32(sm);
    int tid=threadIdx.x, lane=tid&31, wid=tid>>5;
    int g=lane>>2, tig=lane&3;
    int wq=wid&1, wk=wid>>1;
    int lrow=lane&15, lcol=lane>>4;
    int b=blockIdx.z, q0=blockIdx.y*128, k0=blockIdx.x*256;
    const __half* Qg=g_Qh+((size_t)b*N_+q0)*CK_;
    const __half* Khg=g_Kh+((size_t)b*N_+k0)*CK_;

    auto issue=[&](int ch, int st){
        uint32_t base = sb + st*SG_STAGE;
        int ck0=ch*64;
        for(int i=tid;i<1024;i+=256){
            int r=i>>3, s=i&7;
            cp16(base+SG_Q + r*144 + s*16, Qg + (size_t)r*CK_ + ck0 + s*8);
        }
        for(int i=tid;i<2048;i+=256){
            int r=i>>3, s=i&7;
            cp16(base+SG_KH + r*144 + s*16, Khg + (size_t)r*CK_ + ck0 + s*8);
        }
    };

    float acc[4][8][4];
    #pragma unroll
    for(int mi=0;mi<4;mi++)
        #pragma unroll
        for(int ni=0;ni<8;ni++)
            #pragma unroll
            for(int e=0;e<4;e++) acc[mi][ni][e]=0.f;

    issue(0,0); CP_COMMIT();
    issue(1,1); CP_COMMIT();
    int st=2;
    for(int ch=0; ch<7; ch++){
        if(ch+2<7){ issue(ch+2,st); CP_COMMIT(); st=(st+1==3)?0:st+1; CP_WAIT2(); }
        else if(ch+1<7){ CP_WAIT1(); }
        else { CP_WAIT0(); }
        __syncthreads();
        uint32_t stg = sb + (ch%3)*SG_STAGE;
        #pragma unroll
        for(int ks=0;ks<4;ks++){
            int kbo = (ks*16 + lcol*8)*2;
            uint32_t bh[8][2];
            #pragma unroll
            for(int nb=0;nb<4;nb++){
                uint32_t r4[4];
                ldm4(r4, stg+SG_KH + (wk*64+nb*16+lrow)*144 + kbo);
                bh[2*nb][0]=r4[0]; bh[2*nb+1][0]=r4[1]; bh[2*nb][1]=r4[2]; bh[2*nb+1][1]=r4[3];
            }
            #pragma unroll
            for(int mi=0;mi<4;mi++){
                uint32_t a[4];
                ldm4(a, stg+SG_Q + (wq*64+mi*16+lrow)*144 + kbo);
                #pragma unroll
                for(int ni=0;ni<8;ni++) mma16816(acc[mi][ni], a, bh[ni]);
            }
        }
        __syncthreads();
    }
    float* So = g_S + ((size_t)b*N_+q0)*N_ + k0;
    #pragma unroll
    for(int mi=0;mi<4;mi++){
        int qr=wq*64+mi*16+g;
        #pragma unroll
        for(int ni=0;ni<8;ni++){
            int kc=wk*64+ni*8+tig*2;
            float2 v0={acc[mi][ni][0],acc[mi][ni][1]};
            float2 v1={acc[mi][ni][2],acc[mi][ni][3]};
            *(float2*)&So[(size_t)qr*N_+kc]     = v0;
            *(float2*)&So[(size_t)(qr+8)*N_+kc] = v1;
        }
    }
}

// ---------------- kernel 4: masked softmax row pass ----------------
__global__ __launch_bounds__(256) void softmax_kernel(const int* __restrict__ cmask,
                                                      const int* __restrict__ smask){
    int b=blockIdx.y, q=blockIdx.x, tid=threadIdx.x;
    const float4* Srow=(const float4*)(g_S+((size_t)b*N_+q)*N_);
    const int4* smr=(const int4*)(smask+b*N_);
    int cm = cmask[b*N_+q]!=0;
    float s[16], mx=-3.4e38f;
    #pragma unroll
    for(int i=0;i<4;i++){
        int k4=tid+i*256;
        float4 v=Srow[k4];
        if(cm){
            int4 m=smr[k4];
            if(m.x==0)v.x=NEGV; if(m.y==0)v.y=NEGV; if(m.z==0)v.z=NEGV; if(m.w==0)v.w=NEGV;
        }
        s[4*i]=v.x;s[4*i+1]=v.y;s[4*i+2]=v.z;s[4*i+3]=v.w;
        mx=fmaxf(mx,fmaxf(fmaxf(v.x,v.y),fmaxf(v.z,v.w)));
    }
    #pragma unroll
    for(int o=16;o;o>>=1) mx=fmaxf(mx,__shfl_xor_sync(~0u,mx,o));
    __shared__ float red[8];
    int w=tid>>5,l=tid&31;
    if(l==0) red[w]=mx;
    __syncthreads();
    float M=red[0];
    #pragma unroll
    for(int i=1;i<8;i++) M=fmaxf(M,red[i]);
    __syncthreads();
    float sum=0.f;
    uint2* Prow=(uint2*)(g_P+((size_t)b*N_+q)*N_);
    #pragma unroll
    for(int i=0;i<4;i++){
        __align__(8) __half h[4];
        #pragma unroll
        for(int j=0;j<4;j++){
            float p=fast_exp(s[4*i+j]-M);
            h[j]=__float2half_rn(p);
            sum+=__half2float(h[j]);
        }
        Prow[tid+i*256]=*(uint2*)h;
    }
    #pragma unroll
    for(int o=16;o;o>>=1) sum+=__shfl_xor_sync(~0u,sum,o);
    if(l==0) red[w]=sum;
    __syncthreads();
    if(tid==0){
        float t=0.f;
        #pragma unroll
        for(int i=0;i<8;i++) t+=red[i];
        g_l[b*N_+q]=t;
    }
}

// ---------------- kernel 5: [mean,m2] = P * VT^T (mma.sync + ldmatrix, 1-term) ----------------
#define PV_P 0
#define PV_V 18432
#define PV_STAGE 55296
#define PV_SMEM (3*PV_STAGE)
__global__ __launch_bounds__(256) void pv_kernel(){
    extern __shared__ char sm[];
    uint32_t sb = smem_to_u32(sm);
    int tid=threadIdx.x, lane=tid&31, wid=tid>>5;
    int g=lane>>2, tig=lane&3;
    int wq=wid&1, wk=wid>>1;
    int lrow=lane&15, lcol=lane>>4;
    int b=blockIdx.z, q0=blockIdx.y*128, j0=blockIdx.x*256;
    const __half* Pg = g_P  + ((size_t)b*N_+q0)*N_;
    const __half* Vg = g_VTh+ ((size_t)b*2*C_+j0)*N_;

    auto issue=[&](int ch, int st){
        uint32_t base = sb + st*PV_STAGE;
        int kk0=ch*64;
        for(int i=tid;i<1024;i+=256){
            int r=i>>3, s=i&7;
            cp16(base+PV_P + r*144 + s*16, Pg + (size_t)r*N_ + kk0 + s*8);
        }
        for(int i=tid;i<2048;i+=256){
            int r=i>>3, s=i&7;
            cp16(base+PV_V + r*144 + s*16, Vg + (size_t)r*N_ + kk0 + s*8);
        }
    };

    float acc[4][8][4];
    #pragma unroll
    for(int mi=0;mi<4;mi++)
        #pragma unroll
        for(int ni=0;ni<8;ni++)
            #pragma unroll
            for(int e=0;e<4;e++) acc[mi][ni][e]=0.f;

    issue(0,0); CP_COMMIT();
    issue(1,1); CP_COMMIT();
    int st=2;
    for(int ch=0; ch<64; ch++){
        if(ch+2<64){ issue(ch+2,st); CP_COMMIT(); st=(st+1==3)?0:st+1; CP_WAIT2(); }
        else if(ch+1<64){ CP_WAIT1(); }
        else { CP_WAIT0(); }
        __syncthreads();
        uint32_t stg = sb + (ch%3)*PV_STAGE;
        #pragma unroll
        for(int ks=0;ks<4;ks++){
            int kbo = (ks*16 + lcol*8)*2;
            uint32_t bh[8][2];
            #pragma unroll
            for(int nb=0;nb<4;nb++){
                uint32_t r4[4];
                ldm4(r4, stg+PV_V + (wk*64+nb*16+lrow)*144 + kbo);
                bh[2*nb][0]=r4[0]; bh[2*nb+1][0]=r4[1]; bh[2*nb][1]=r4[2]; bh[2*nb+1][1]=r4[3];
            }
            #pragma unroll
            for(int mi=0;mi<4;mi++){
                uint32_t a[4];
                ldm4(a, stg+PV_P + (wq*64+mi*16+lrow)*144 + kbo);
                #pragma unroll
                for(int ni=0;ni<8;ni++) mma16816(acc[mi][ni], a, bh[ni]);
            }
        }
        __syncthreads();
    }
    float* Ob = g_O + ((size_t)b*N_+q0)*(2*C_) + j0;
    #pragma unroll
    for(int mi=0;mi<4;mi++){
        int qr=wq*64+mi*16+g;
        #pragma unroll
        for(int ni=0;ni<8;ni++){
            int jc=wk*64+ni*8+tig*2;
            float2 v0={acc[mi][ni][0],acc[mi][ni][1]};
            float2 v1={acc[mi][ni][2],acc[mi][ni][3]};
            *(float2*)&Ob[(size_t)qr*(2*C_)+jc]     = v0;
            *(float2*)&Ob[(size_t)(qr+8)*(2*C_)+jc] = v1;
        }
    }
}

// ---------------- kernel 6: finalize ----------------
__global__ __launch_bounds__(256) void final_kernel(const float* __restrict__ content,
                                                    float* __restrict__ out){
    int b=blockIdx.z, c=blockIdx.y;
    int n=(blockIdx.x*256+threadIdx.x)*4;
    const float* Ob=g_O+(size_t)b*N_*(2*C_);
    float4 l4=*(const float4*)&g_l[b*N_+n];
    float lv[4]={l4.x,l4.y,l4.z,l4.w};
    float cmv=g_cmean[b*C_+c], cr=g_crstd[b*C_+c];
    size_t oi=((size_t)(b*C_+c))*N_+n;
    float4 cx=*(const float4*)&content[oi];
    float ci[4]={cx.x,cx.y,cx.z,cx.w};
    float res[4];
    #pragma unroll
    for(int i=0;i<4;i++){
        float2 mv=*(const float2*)&Ob[(size_t)(n+i)*(2*C_)+2*c];
        float inv=1.0f/lv[i];
        float mean=mv.x*inv, m2=mv.y*inv;
        float sd=sqrtf(fmaxf(m2-mean*mean,0.f));
        res[i]=sd*(ci[i]-cmv)*cr+mean;
    }
    float4 ro={res[0],res[1],res[2],res[3]};
    *(float4*)&out[oi]=ro;
}

// ---------------- launch ----------------
extern "C" void kernel_launch(void* const* d_in, const int* in_sizes, int n_in,
                              void* d_out, int out_size){
    const float* content     = (const float*)d_in[0];
    const float* style       = (const float*)d_in[1];
    const float* content_key = (const float*)d_in[2];
    const float* style_key   = (const float*)d_in[3];
    const int*   cmask       = (const int*)d_in[4];
    const int*   smask       = (const int*)d_in[5];
    const float* Wf=(const float*)d_in[6];  const float* bf=(const float*)d_in[7];
    const float* Wg=(const float*)d_in[8];  const float* bg=(const float*)d_in[9];
    const float* Wh=(const float*)d_in[10]; const float* bh=(const float*)d_in[11];
    float* out=(float*)d_out;

    __half *qh,*kh,*vth,*ckh,*ckl,*skh,*skl,*wfh,*wfl,*wgh,*wgl;
    cudaGetSymbolAddress((void**)&qh,  g_Qh);
    cudaGetSymbolAddress((void**)&kh,  g_Kh);
    cudaGetSymbolAddress((void**)&vth, g_VTh);
    cudaGetSymbolAddress((void**)&ckh, g_CKh); cudaGetSymbolAddress((void**)&ckl, g_CKl);
    cudaGetSymbolAddress((void**)&skh, g_SKh); cudaGetSymbolAddress((void**)&skl, g_SKl);
    cudaGetSymbolAddress((void**)&wfh, g_Wfh); cudaGetSymbolAddress((void**)&wfl, g_Wfl);
    cudaGetSymbolAddress((void**)&wgh, g_Wgh); cudaGetSymbolAddress((void**)&wgl, g_Wgl);
    cudaFuncSetAttribute(proj_mma_kernel, cudaFuncAttributeMaxDynamicSharedMemorySize, PM_SMEM);
    cudaFuncSetAttribute(sgemm_kernel, cudaFuncAttributeMaxDynamicSharedMemorySize, SG_SMEM);
    cudaFuncSetAttribute(pv_kernel,    cudaFuncAttributeMaxDynamicSharedMemorySize, PV_SMEM);

    int nx4 = B_*CK_*N_/4, nw4 = CK_*CK_/4;
    stats_kernel<<<B_*C_, 256>>>(content);
    split_kernel<<<(nx4+255)/256, 256>>>(content_key, ckh, ckl, nx4);
    split_kernel<<<(nx4+255)/256, 256>>>(style_key,   skh, skl, nx4);
    split_kernel<<<(nw4+255)/256, 256>>>(Wf, wfh, wfl, nw4);
    split_kernel<<<(nw4+255)/256, 256>>>(Wg, wgh, wgl, nw4);
    proj_mma_kernel<<<dim3(32, 7, B_), 256, PM_SMEM>>>(ckh, ckl, wfh, wfl, bf, qh);
    proj_mma_kernel<<<dim3(32, 7, B_), 256, PM_SMEM>>>(skh, skl, wgh, wgl, bg, kh);
    projv_kernel<C_><<<dim3(32, 4, B_), 256>>>(style, Wh, bh, vth);
    sgemm_kernel<<<dim3(16, 32, B_), 256, SG_SMEM>>>();
    softmax_kernel<<<dim3(N_, B_), 256>>>(cmask, smask);
    pv_kernel<<<dim3(2, 32, B_), 256, PV_SMEM>>>();
    final_kernel<<<dim3(4, C_, B_), 256>>>(content, out);
}

// round 9
// speedup vs baseline: 1.3242x; 1.3242x over previous
#include <cuda_runtime.h>
#include <cuda_fp16.h>
#include <cstdint>

#define B_   4
#define C_   256
#define CK_  448
#define N_   4096
#define NEGV (-1e15f)

// ---------------- device scratch ----------------
__device__ __half g_Qh[(size_t)B_*N_*CK_];
__device__ __half g_Kh[(size_t)B_*N_*CK_];
__device__ __half g_VTh[(size_t)B_*2*C_*N_];   // [b][j][n], j=2c:v, 2c+1:v^2
__device__ __half g_S[(size_t)B_*N_*N_];       // [b][q][k]  fp16 scores
__device__ __half g_P[(size_t)B_*N_*N_];       // [b][q][k]
__device__ float  g_l[B_*N_];
__device__ float  g_O[(size_t)B_*N_*2*C_];     // [b][q][j]
__device__ float  g_cmean[B_*C_], g_crstd[B_*C_];

// ---------------- f32x2 helpers (proj GEMM) ----------------
typedef unsigned long long u64v;
__device__ __forceinline__ u64v pk2(float x, float y){u64v r;asm("mov.b64 %0,{%1,%2};":"=l"(r):"f"(x),"f"(y));return r;}
__device__ __forceinline__ void upk2(u64v v,float&x,float&y){asm("mov.b64 {%0,%1},%2;":"=f"(x),"=f"(y):"l"(v));}
__device__ __forceinline__ u64v ffma2(u64v a,u64v b,u64v c){u64v d;asm("fma.rn.f32x2 %0,%1,%2,%3;":"=l"(d):"l"(a),"l"(b),"l"(c));return d;}

// ---------------- mma.sync / ldmatrix / cp.async ----------------
__device__ __forceinline__ uint32_t smem_to_u32(const void*p){
    uint32_t a;asm("{ .reg .u64 t; cvta.to.shared.u64 t, %1; cvt.u32.u64 %0, t; }":"=r"(a):"l"(p));return a;}
__device__ __forceinline__ void mma16816(float* c, const uint32_t* a, const uint32_t* b){
    asm volatile("mma.sync.aligned.m16n8k16.row.col.f32.f16.f16.f32 "
        "{%0,%1,%2,%3}, {%4,%5,%6,%7}, {%8,%9}, {%0,%1,%2,%3};"
        : "+f"(c[0]),"+f"(c[1]),"+f"(c[2]),"+f"(c[3])
        : "r"(a[0]),"r"(a[1]),"r"(a[2]),"r"(a[3]), "r"(b[0]),"r"(b[1]));
}
__device__ __forceinline__ void ldm4(uint32_t* r, uint32_t addr){
    asm volatile("ldmatrix.sync.aligned.m8n8.x4.shared.b16 {%0,%1,%2,%3}, [%4];"
        :"=r"(r[0]),"=r"(r[1]),"=r"(r[2]),"=r"(r[3]):"r"(addr));
}
__device__ __forceinline__ void cp16(uint32_t dst, const void* src){
    asm volatile("cp.async.cg.shared.global [%0], [%1], 16;" :: "r"(dst), "l"(src));
}
#define CP_COMMIT() asm volatile("cp.async.commit_group;" ::: "memory")
#define CP_WAIT2()  asm volatile("cp.async.wait_group 2;" ::: "memory")
#define CP_WAIT1()  asm volatile("cp.async.wait_group 1;" ::: "memory")
#define CP_WAIT0()  asm volatile("cp.async.wait_group 0;" ::: "memory")

// ---------------- fast exp on fma pipe ----------------
__device__ __forceinline__ float fast_exp(float x){
    float t = fmaxf(x * 1.4426950408889634f, -126.0f);
    float fi = t + 12582912.0f;
    int i = __float_as_int(fi) - 0x4B400000;
    float f = t - (fi - 12582912.0f);
    float p = 1.5424236e-4f;
    p = fmaf(p,f,1.3333558e-3f); p = fmaf(p,f,9.6181291e-3f);
    p = fmaf(p,f,5.5504109e-2f); p = fmaf(p,f,2.4022651e-1f);
    p = fmaf(p,f,6.9314718e-1f); p = fmaf(p,f,1.0f);
    return __int_as_float(__float_as_int(p) + (i<<23));
}

// ---------------- kernel 1: content stats ----------------
__global__ __launch_bounds__(256) void stats_kernel(const float* __restrict__ content){
    int bc = blockIdx.x, tid = threadIdx.x;
    const float4* x = (const float4*)(content + (size_t)bc*N_);
    float s=0.f,q=0.f;
    for(int i=tid;i<N_/4;i+=256){float4 v=x[i];s+=v.x+v.y+v.z+v.w;q+=v.x*v.x+v.y*v.y+v.z*v.z+v.w*v.w;}
    #pragma unroll
    for(int o=16;o;o>>=1){s+=__shfl_xor_sync(~0u,s,o);q+=__shfl_xor_sync(~0u,q,o);}
    __shared__ float ss[8],qq[8];
    int w=tid>>5,l=tid&31;
    if(l==0){ss[w]=s;qq[w]=q;}
    __syncthreads();
    if(tid==0){
        float S=0,Q=0;
        #pragma unroll
        for(int i=0;i<8;i++){S+=ss[i];Q+=qq[i];}
        float mean=S/(float)N_;
        float var=(Q-(float)N_*mean*mean)/(float)(N_-1);
        g_cmean[bc]=mean; g_crstd[bc]=rsqrtf(var+1e-5f);
    }
}

// ---------------- kernel 2: projection (SIMT, cp.async double-buffered) ----------------
// CTA 128n x 64o; thread 8n x 4o.
// MODE 0: Yh[b][n][CK_] fp16. MODE 1: VT[b][2o(+1)][n] with v and v^2.
template<int CIN, int MODE>
__global__ __launch_bounds__(256) void proj_kernel(const float* __restrict__ X,
                                                   const float* __restrict__ W,
                                                   const float* __restrict__ bias,
                                                   __half* __restrict__ Yh){
    __shared__ float Xs[2][32*128];
    __shared__ float Ws[2][32*64];
    int b=blockIdx.z, n0=blockIdx.x*128, o0=blockIdx.y*64;
    int tid=threadIdx.x, tx=tid&15, ty=tid>>4;
    uint32_t sbX = smem_to_u32(&Xs[0][0]);
    const int nblk = CIN/32;

    auto issueX=[&](int blk, int st){
        const float* src = X + ((size_t)(b*CIN+blk*32))*N_ + n0;
        uint32_t base = sbX + st*16384;
        for(int e=tid;e<1024;e+=256){
            int cc=e>>5, s=e&31;
            cp16(base + cc*512 + s*16, src + (size_t)cc*N_ + s*4);
        }
    };
    float4 wr[2];
    auto ldW=[&](int blk){
        #pragma unroll
        for(int i=0;i<2;i++){
            int e=tid+i*256, oo=e>>3, c4=(e&7)<<2;
            wr[i] = *(const float4*)&W[(size_t)(o0+oo)*CIN + blk*32 + c4];
        }
    };
    auto stW=[&](int st){
        #pragma unroll
        for(int i=0;i<2;i++){
            int e=tid+i*256, oo=e>>3, c4=(e&7)<<2;
            Ws[st][(c4+0)*64+oo]=wr[i].x; Ws[st][(c4+1)*64+oo]=wr[i].y;
            Ws[st][(c4+2)*64+oo]=wr[i].z; Ws[st][(c4+3)*64+oo]=wr[i].w;
        }
    };

    u64v acc2[4][4];
    #pragma unroll
    for(int p=0;p<4;p++)
        #pragma unroll
        for(int j=0;j<4;j++) acc2[p][j]=0ull;

    issueX(0,0); CP_COMMIT();
    ldW(0); stW(0);
    for(int blk=0; blk<nblk; blk++){
        int cur = blk&1;
        if(blk+1<nblk){ issueX(blk+1, cur^1); CP_COMMIT(); ldW(blk+1); }
        if(blk+1<nblk) CP_WAIT1(); else CP_WAIT0();
        __syncthreads();
        if(blk+1<nblk) stW(cur^1);
        const float* Xc = &Xs[cur][0];
        const float* Wc = &Ws[cur][0];
        #pragma unroll 4
        for(int cc=0;cc<32;cc++){
            const u64v* xr=(const u64v*)&Xc[cc*128+ty*8];
            u64v x0=xr[0], x1=xr[1], x2=xr[2], x3=xr[3];
            float4 w4=*(const float4*)&Wc[cc*64+tx*4];
            u64v w0=pk2(w4.x,w4.x),w1=pk2(w4.y,w4.y),w2=pk2(w4.z,w4.z),w3=pk2(w4.w,w4.w);
            acc2[0][0]=ffma2(x0,w0,acc2[0][0]); acc2[0][1]=ffma2(x0,w1,acc2[0][1]);
            acc2[0][2]=ffma2(x0,w2,acc2[0][2]); acc2[0][3]=ffma2(x0,w3,acc2[0][3]);
            acc2[1][0]=ffma2(x1,w0,acc2[1][0]); acc2[1][1]=ffma2(x1,w1,acc2[1][1]);
            acc2[1][2]=ffma2(x1,w2,acc2[1][2]); acc2[1][3]=ffma2(x1,w3,acc2[1][3]);
            acc2[2][0]=ffma2(x2,w0,acc2[2][0]); acc2[2][1]=ffma2(x2,w1,acc2[2][1]);
            acc2[2][2]=ffma2(x2,w2,acc2[2][2]); acc2[2][3]=ffma2(x2,w3,acc2[2][3]);
            acc2[3][0]=ffma2(x3,w0,acc2[3][0]); acc2[3][1]=ffma2(x3,w1,acc2[3][1]);
            acc2[3][2]=ffma2(x3,w2,acc2[3][2]); acc2[3][3]=ffma2(x3,w3,acc2[3][3]);
        }
        __syncthreads();
    }
    float a[8][4];
    #pragma unroll
    for(int p=0;p<4;p++)
        #pragma unroll
        for(int j=0;j<4;j++) upk2(acc2[p][j],a[2*p][j],a[2*p+1][j]);
    float4 bo=*(const float4*)&bias[o0+tx*4];
    float bb[4]={bo.x,bo.y,bo.z,bo.w};
    if(MODE==0){
        #pragma unroll
        for(int i=0;i<8;i++){
            __align__(8) __half hh[4];
            #pragma unroll
            for(int j=0;j<4;j++) hh[j]=__float2half_rn(a[i][j]+bb[j]);
            size_t base=((size_t)(b*N_)+n0+ty*8+i)*CK_+o0+tx*4;
            *(uint2*)&Yh[base]=*(uint2*)hh;
        }
    } else {
        #pragma unroll
        for(int j=0;j<4;j++){
            __align__(16) __half vh[8], wh[8];
            #pragma unroll
            for(int i=0;i<8;i++){
                float y=a[i][j]+bb[j];
                vh[i]=__float2half_rn(y);
                wh[i]=__float2half_rn(y*y);
            }
            int o=o0+tx*4+j;
            size_t rv=((size_t)b*(2*C_)+2*o)*N_+n0+ty*8;
            *(uint4*)&Yh[rv]=*(uint4*)vh; *(uint4*)&Yh[rv+N_]=*(uint4*)wh;
        }
    }
}

// ---------------- kernel 3: S = Q K^T  (mma.sync + ldmatrix, fp16 out, 3-stage) ----------------
#define SG_Q  0
#define SG_KH 18432
#define SG_STAGE 55296
#define SG_SMEM (3*SG_STAGE)
__global__ __launch_bounds__(256) void sgemm_kernel(){
    extern __shared__ char sm[];
    uint32_t sb = smem_to_u32(sm);
    int tid=threadIdx.x, lane=tid&31, wid=tid>>5;
    int g=lane>>2, tig=lane&3;
    int wq=wid&1, wk=wid>>1;
    int lrow=lane&15, lcol=lane>>4;
    int b=blockIdx.z, q0=blockIdx.y*128, k0=blockIdx.x*256;
    const __half* Qg=g_Qh+((size_t)b*N_+q0)*CK_;
    const __half* Khg=g_Kh+((size_t)b*N_+k0)*CK_;

    auto issue=[&](int ch, int st){
        uint32_t base = sb + st*SG_STAGE;
        int ck0=ch*64;
        for(int i=tid;i<1024;i+=256){
            int r=i>>3, s=i&7;
            cp16(base+SG_Q + r*144 + s*16, Qg + (size_t)r*CK_ + ck0 + s*8);
        }
        for(int i=tid;i<2048;i+=256){
            int r=i>>3, s=i&7;
            cp16(base+SG_KH + r*144 + s*16, Khg + (size_t)r*CK_ + ck0 + s*8);
        }
    };

    float acc[4][8][4];
    #pragma unroll
    for(int mi=0;mi<4;mi++)
        #pragma unroll
        for(int ni=0;ni<8;ni++)
            #pragma unroll
            for(int e=0;e<4;e++) acc[mi][ni][e]=0.f;

    issue(0,0); CP_COMMIT();
    issue(1,1); CP_COMMIT();
    int st=2;
    for(int ch=0; ch<7; ch++){
        if(ch+2<7){ issue(ch+2,st); CP_COMMIT(); st=(st+1==3)?0:st+1; CP_WAIT2(); }
        else if(ch+1<7){ CP_WAIT1(); }
        else { CP_WAIT0(); }
        __syncthreads();
        uint32_t stg = sb + (ch%3)*SG_STAGE;
        #pragma unroll
        for(int ks=0;ks<4;ks++){
            int kbo = (ks*16 + lcol*8)*2;
            uint32_t bh[8][2];
            #pragma unroll
            for(int nb=0;nb<4;nb++){
                uint32_t r4[4];
                ldm4(r4, stg+SG_KH + (wk*64+nb*16+lrow)*144 + kbo);
                bh[2*nb][0]=r4[0]; bh[2*nb+1][0]=r4[1]; bh[2*nb][1]=r4[2]; bh[2*nb+1][1]=r4[3];
            }
            #pragma unroll
            for(int mi=0;mi<4;mi++){
                uint32_t a[4];
                ldm4(a, stg+SG_Q + (wq*64+mi*16+lrow)*144 + kbo);
                #pragma unroll
                for(int ni=0;ni<8;ni++) mma16816(acc[mi][ni], a, bh[ni]);
            }
        }
        __syncthreads();
    }
    __half* So = g_S + ((size_t)b*N_+q0)*N_ + k0;
    #pragma unroll
    for(int mi=0;mi<4;mi++){
        int qr=wq*64+mi*16+g;
        #pragma unroll
        for(int ni=0;ni<8;ni++){
            int kc=wk*64+ni*8+tig*2;
            *(__half2*)&So[(size_t)qr*N_+kc]     = __floats2half2_rn(acc[mi][ni][0],acc[mi][ni][1]);
            *(__half2*)&So[(size_t)(qr+8)*N_+kc] = __floats2half2_rn(acc[mi][ni][2],acc[mi][ni][3]);
        }
    }
}

// ---------------- kernel 4: masked softmax row pass (fp16 S in, fp16 P out) ----------------
__global__ __launch_bounds__(256) void softmax_kernel(const int* __restrict__ cmask,
                                                      const int* __restrict__ smask){
    int b=blockIdx.y, q=blockIdx.x, tid=threadIdx.x;
    const uint4* Srow=(const uint4*)(g_S+((size_t)b*N_+q)*N_);   // 512 x 8 halfs
    const int4* smr=(const int4*)(smask+b*N_);
    int cm = cmask[b*N_+q]!=0;
    float s[16], mx=-3.4e38f;
    #pragma unroll
    for(int i=0;i<2;i++){
        int idx=tid+i*256;
        uint4 v=Srow[idx];
        __half2 h2[4]; *(uint4*)h2 = v;
        float2 f0=__half22float2(h2[0]), f1=__half22float2(h2[1]);
        float2 f2=__half22float2(h2[2]), f3=__half22float2(h2[3]);
        float sv[8]={f0.x,f0.y,f1.x,f1.y,f2.x,f2.y,f3.x,f3.y};
        if(cm){
            int4 m0=smr[2*idx], m1=smr[2*idx+1];
            if(m0.x==0)sv[0]=NEGV; if(m0.y==0)sv[1]=NEGV; if(m0.z==0)sv[2]=NEGV; if(m0.w==0)sv[3]=NEGV;
            if(m1.x==0)sv[4]=NEGV; if(m1.y==0)sv[5]=NEGV; if(m1.z==0)sv[6]=NEGV; if(m1.w==0)sv[7]=NEGV;
        }
        #pragma unroll
        for(int j=0;j<8;j++){ s[8*i+j]=sv[j]; mx=fmaxf(mx,sv[j]); }
    }
    #pragma unroll
    for(int o=16;o;o>>=1) mx=fmaxf(mx,__shfl_xor_sync(~0u,mx,o));
    __shared__ float red[8];
    int w=tid>>5,l=tid&31;
    if(l==0) red[w]=mx;
    __syncthreads();
    float M=red[0];
    #pragma unroll
    for(int i=1;i<8;i++) M=fmaxf(M,red[i]);
    __syncthreads();
    float sum=0.f;
    uint4* Prow=(uint4*)(g_P+((size_t)b*N_+q)*N_);
    #pragma unroll
    for(int i=0;i<2;i++){
        __align__(16) __half h[8];
        #pragma unroll
        for(int j=0;j<8;j++){
            float p=fast_exp(s[8*i+j]-M);
            h[j]=__float2half_rn(p);
            sum+=__half2float(h[j]);
        }
        Prow[tid+i*256]=*(uint4*)h;
    }
    #pragma unroll
    for(int o=16;o;o>>=1) sum+=__shfl_xor_sync(~0u,sum,o);
    if(l==0) red[w]=sum;
    __syncthreads();
    if(tid==0){
        float t=0.f;
        #pragma unroll
        for(int i=0;i<8;i++) t+=red[i];
        g_l[b*N_+q]=t;
    }
}

// ---------------- kernel 5: [mean,m2] = P * VT^T (mma.sync + ldmatrix) ----------------
#define PV_P 0
#define PV_V 18432
#define PV_STAGE 55296
#define PV_SMEM (3*PV_STAGE)
__global__ __launch_bounds__(256) void pv_kernel(){
    extern __shared__ char sm[];
    uint32_t sb = smem_to_u32(sm);
    int tid=threadIdx.x, lane=tid&31, wid=tid>>5;
    int g=lane>>2, tig=lane&3;
    int wq=wid&1, wk=wid>>1;
    int lrow=lane&15, lcol=lane>>4;
    int b=blockIdx.z, q0=blockIdx.y*128, j0=blockIdx.x*256;
    const __half* Pg = g_P  + ((size_t)b*N_+q0)*N_;
    const __half* Vg = g_VTh+ ((size_t)b*2*C_+j0)*N_;

    auto issue=[&](int ch, int st){
        uint32_t base = sb + st*PV_STAGE;
        int kk0=ch*64;
        for(int i=tid;i<1024;i+=256){
            int r=i>>3, s=i&7;
            cp16(base+PV_P + r*144 + s*16, Pg + (size_t)r*N_ + kk0 + s*8);
        }
        for(int i=tid;i<2048;i+=256){
            int r=i>>3, s=i&7;
            cp16(base+PV_V + r*144 + s*16, Vg + (size_t)r*N_ + kk0 + s*8);
        }
    };

    float acc[4][8][4];
    #pragma unroll
    for(int mi=0;mi<4;mi++)
        #pragma unroll
        for(int ni=0;ni<8;ni++)
            #pragma unroll
            for(int e=0;e<4;e++) acc[mi][ni][e]=0.f;

    issue(0,0); CP_COMMIT();
    issue(1,1); CP_COMMIT();
    int st=2;
    for(int ch=0; ch<64; ch++){
        if(ch+2<64){ issue(ch+2,st); CP_COMMIT(); st=(st+1==3)?0:st+1; CP_WAIT2(); }
        else if(ch+1<64){ CP_WAIT1(); }
        else { CP_WAIT0(); }
        __syncthreads();
        uint32_t stg = sb + (ch%3)*PV_STAGE;
        #pragma unroll
        for(int ks=0;ks<4;ks++){
            int kbo = (ks*16 + lcol*8)*2;
            uint32_t bh[8][2];
            #pragma unroll
            for(int nb=0;nb<4;nb++){
                uint32_t r4[4];
                ldm4(r4, stg+PV_V + (wk*64+nb*16+lrow)*144 + kbo);
                bh[2*nb][0]=r4[0]; bh[2*nb+1][0]=r4[1]; bh[2*nb][1]=r4[2]; bh[2*nb+1][1]=r4[3];
            }
            #pragma unroll
            for(int mi=0;mi<4;mi++){
                uint32_t a[4];
                ldm4(a, stg+PV_P + (wq*64+mi*16+lrow)*144 + kbo);
                #pragma unroll
                for(int ni=0;ni<8;ni++) mma16816(acc[mi][ni], a, bh[ni]);
            }
        }
        __syncthreads();
    }
    float* Ob = g_O + ((size_t)b*N_+q0)*(2*C_) + j0;
    #pragma unroll
    for(int mi=0;mi<4;mi++){
        int qr=wq*64+mi*16+g;
        #pragma unroll
        for(int ni=0;ni<8;ni++){
            int jc=wk*64+ni*8+tig*2;
            float2 v0={acc[mi][ni][0],acc[mi][ni][1]};
            float2 v1={acc[mi][ni][2],acc[mi][ni][3]};
            *(float2*)&Ob[(size_t)qr*(2*C_)+jc]     = v0;
            *(float2*)&Ob[(size_t)(qr+8)*(2*C_)+jc] = v1;
        }
    }
}

// ---------------- kernel 6: finalize ----------------
__global__ __launch_bounds__(256) void final_kernel(const float* __restrict__ content,
                                                    float* __restrict__ out){
    int b=blockIdx.z, c=blockIdx.y;
    int n=(blockIdx.x*256+threadIdx.x)*4;
    const float* Ob=g_O+(size_t)b*N_*(2*C_);
    float4 l4=*(const float4*)&g_l[b*N_+n];
    float lv[4]={l4.x,l4.y,l4.z,l4.w};
    float cmv=g_cmean[b*C_+c], cr=g_crstd[b*C_+c];
    size_t oi=((size_t)(b*C_+c))*N_+n;
    float4 cx=*(const float4*)&content[oi];
    float ci[4]={cx.x,cx.y,cx.z,cx.w};
    float res[4];
    #pragma unroll
    for(int i=0;i<4;i++){
        float2 mv=*(const float2*)&Ob[(size_t)(n+i)*(2*C_)+2*c];
        float inv=1.0f/lv[i];
        float mean=mv.x*inv, m2=mv.y*inv;
        float sd=sqrtf(fmaxf(m2-mean*mean,0.f));
        res[i]=sd*(ci[i]-cmv)*cr+mean;
    }
    float4 ro={res[0],res[1],res[2],res[3]};
    *(float4*)&out[oi]=ro;
}

// ---------------- launch ----------------
extern "C" void kernel_launch(void* const* d_in, const int* in_sizes, int n_in,
                              void* d_out, int out_size){
    const float* content     = (const float*)d_in[0];
    const float* style       = (const float*)d_in[1];
    const float* content_key = (const float*)d_in[2];
    const float* style_key   = (const float*)d_in[3];
    const int*   cmask       = (const int*)d_in[4];
    const int*   smask       = (const int*)d_in[5];
    const float* Wf=(const float*)d_in[6];  const float* bf=(const float*)d_in[7];
    const float* Wg=(const float*)d_in[8];  const float* bg=(const float*)d_in[9];
    const float* Wh=(const float*)d_in[10]; const float* bh=(const float*)d_in[11];
    float* out=(float*)d_out;

    __half *qh,*kh,*vth;
    cudaGetSymbolAddress((void**)&qh,  g_Qh);
    cudaGetSymbolAddress((void**)&kh,  g_Kh);
    cudaGetSymbolAddress((void**)&vth, g_VTh);
    cudaFuncSetAttribute(sgemm_kernel, cudaFuncAttributeMaxDynamicSharedMemorySize, SG_SMEM);
    cudaFuncSetAttribute(pv_kernel,    cudaFuncAttributeMaxDynamicSharedMemorySize, PV_SMEM);

    stats_kernel<<<B_*C_, 256>>>(content);
    proj_kernel<CK_,0><<<dim3(32, 7, B_), 256>>>(content_key, Wf, bf, qh);
    proj_kernel<CK_,0><<<dim3(32, 7, B_), 256>>>(style_key,   Wg, bg, kh);
    proj_kernel<C_, 1><<<dim3(32, 4, B_), 256>>>(style,       Wh, bh, vth);
    sgemm_kernel<<<dim3(16, 32, B_), 256, SG_SMEM>>>();
    softmax_kernel<<<dim3(N_, B_), 256>>>(cmask, smask);
    pv_kernel<<<dim3(2, 32, B_), 256, PV_SMEM>>>();
    final_kernel<<<dim3(4, C_, B_), 256>>>(content, out);
}

// round 10
// speedup vs baseline: 1.5463x; 1.1677x over previous
#include <cuda_runtime.h>
#include <cuda_fp16.h>
#include <cstdint>

#define B_   4
#define C_   256
#define CK_  448
#define N_   4096
#define NEGV (-1e15f)

// ---------------- device scratch ----------------
__device__ __half g_Qh[(size_t)B_*N_*CK_];
__device__ __half g_Kh[(size_t)B_*N_*CK_];
__device__ __half g_VTh[(size_t)B_*2*C_*N_];   // [b][j][n], j=2c:v, 2c+1:v^2
__device__ float  g_S[(size_t)B_*N_*N_];       // [b][q][k] fp32 scores
__device__ __half g_P[(size_t)B_*N_*N_];       // [b][q][k]
__device__ float  g_l[B_*N_];
__device__ float  g_O[(size_t)B_*N_*2*C_];     // [b][q][j]
__device__ float  g_cmean[B_*C_], g_crstd[B_*C_];
// transposed fp16 hi/lo key inputs: [b][n][c]
__device__ __half g_CTh[(size_t)B_*N_*CK_], g_CTl[(size_t)B_*N_*CK_];
__device__ __half g_STh[(size_t)B_*N_*CK_], g_STl[(size_t)B_*N_*CK_];
__device__ __half g_Wf16[CK_*CK_], g_Wg16[CK_*CK_];

// ---------------- f32x2 helpers (proj V GEMM) ----------------
typedef unsigned long long u64v;
__device__ __forceinline__ u64v pk2(float x, float y){u64v r;asm("mov.b64 %0,{%1,%2};":"=l"(r):"f"(x),"f"(y));return r;}
__device__ __forceinline__ void upk2(u64v v,float&x,float&y){asm("mov.b64 {%0,%1},%2;":"=f"(x),"=f"(y):"l"(v));}
__device__ __forceinline__ u64v ffma2(u64v a,u64v b,u64v c){u64v d;asm("fma.rn.f32x2 %0,%1,%2,%3;":"=l"(d):"l"(a),"l"(b),"l"(c));return d;}

// ---------------- mma.sync / ldmatrix / cp.async ----------------
__device__ __forceinline__ uint32_t smem_to_u32(const void*p){
    uint32_t a;asm("{ .reg .u64 t; cvta.to.shared.u64 t, %1; cvt.u32.u64 %0, t; }":"=r"(a):"l"(p));return a;}
__device__ __forceinline__ void mma16816(float* c, const uint32_t* a, const uint32_t* b){
    asm volatile("mma.sync.aligned.m16n8k16.row.col.f32.f16.f16.f32 "
        "{%0,%1,%2,%3}, {%4,%5,%6,%7}, {%8,%9}, {%0,%1,%2,%3};"
        : "+f"(c[0]),"+f"(c[1]),"+f"(c[2]),"+f"(c[3])
        : "r"(a[0]),"r"(a[1]),"r"(a[2]),"r"(a[3]), "r"(b[0]),"r"(b[1]));
}
__device__ __forceinline__ void ldm4(uint32_t* r, uint32_t addr){
    asm volatile("ldmatrix.sync.aligned.m8n8.x4.shared.b16 {%0,%1,%2,%3}, [%4];"
        :"=r"(r[0]),"=r"(r[1]),"=r"(r[2]),"=r"(r[3]):"r"(addr));
}
__device__ __forceinline__ void cp16(uint32_t dst, const void* src){
    asm volatile("cp.async.cg.shared.global [%0], [%1], 16;" :: "r"(dst), "l"(src));
}
#define CP_COMMIT() asm volatile("cp.async.commit_group;" ::: "memory")
#define CP_WAIT2()  asm volatile("cp.async.wait_group 2;" ::: "memory")
#define CP_WAIT1()  asm volatile("cp.async.wait_group 1;" ::: "memory")
#define CP_WAIT0()  asm volatile("cp.async.wait_group 0;" ::: "memory")

// ---------------- fast exp on fma pipe ----------------
__device__ __forceinline__ float fast_exp(float x){
    float t = fmaxf(x * 1.4426950408889634f, -126.0f);
    float fi = t + 12582912.0f;
    int i = __float_as_int(fi) - 0x4B400000;
    float f = t - (fi - 12582912.0f);
    float p = 1.5424236e-4f;
    p = fmaf(p,f,1.3333558e-3f); p = fmaf(p,f,9.6181291e-3f);
    p = fmaf(p,f,5.5504109e-2f); p = fmaf(p,f,2.4022651e-1f);
    p = fmaf(p,f,6.9314718e-1f); p = fmaf(p,f,1.0f);
    return __int_as_float(__float_as_int(p) + (i<<23));
}
__device__ __forceinline__ void hsplit(float y, __half& h, __half& l){
    h = __float2half_rn(y); l = __float2half_rn(y - __half2float(h));
}

// ---------------- kernel 0a: transpose fp32 [b][c][n] -> fp16 hi/lo [b][n][c] ----------------
__global__ __launch_bounds__(256) void transpose_kernel(const float* __restrict__ X,
                                                        __half* __restrict__ Th,
                                                        __half* __restrict__ Tl){
    __shared__ float ts[32][33];
    int b=blockIdx.z, n0=blockIdx.x*32, c0=blockIdx.y*32;
    int tid=threadIdx.x;
    int nl=tid&31, cb=tid>>5;
    #pragma unroll
    for(int i=0;i<4;i++){
        int c=cb+i*8;
        ts[c][nl]=X[((size_t)(b*CK_)+c0+c)*N_ + n0+nl];
    }
    __syncthreads();
    int n=tid>>3, c4=(tid&7)*4;
    __align__(8) __half hh[4], hl[4];
    #pragma unroll
    for(int j=0;j<4;j++) hsplit(ts[c4+j][n], hh[j], hl[j]);
    size_t o=((size_t)(b*N_)+n0+n)*CK_ + c0+c4;
    *(uint2*)&Th[o]=*(uint2*)hh;
    *(uint2*)&Tl[o]=*(uint2*)hl;
}

// ---------------- kernel 0b: fp32 -> fp16 (weights) ----------------
__global__ __launch_bounds__(256) void whalf_kernel(const float* __restrict__ src,
                                                    __half* __restrict__ dst, int n4){
    int i=blockIdx.x*256+threadIdx.x;
    if(i>=n4) return;
    float4 v=((const float4*)src)[i];
    __align__(8) __half h[4];
    h[0]=__float2half_rn(v.x); h[1]=__float2half_rn(v.y);
    h[2]=__float2half_rn(v.z); h[3]=__float2half_rn(v.w);
    ((uint2*)dst)[i]=*(uint2*)h;
}

// ---------------- kernel 1: content stats ----------------
__global__ __launch_bounds__(256) void stats_kernel(const float* __restrict__ content){
    int bc = blockIdx.x, tid = threadIdx.x;
    const float4* x = (const float4*)(content + (size_t)bc*N_);
    float s=0.f,q=0.f;
    for(int i=tid;i<N_/4;i+=256){float4 v=x[i];s+=v.x+v.y+v.z+v.w;q+=v.x*v.x+v.y*v.y+v.z*v.z+v.w*v.w;}
    #pragma unroll
    for(int o=16;o;o>>=1){s+=__shfl_xor_sync(~0u,s,o);q+=__shfl_xor_sync(~0u,q,o);}
    __shared__ float ss[8],qq[8];
    int w=tid>>5,l=tid&31;
    if(l==0){ss[w]=s;qq[w]=q;}
    __syncthreads();
    if(tid==0){
        float S=0,Q=0;
        #pragma unroll
        for(int i=0;i<8;i++){S+=ss[i];Q+=qq[i];}
        float mean=S/(float)N_;
        float var=(Q-(float)N_*mean*mean)/(float)(N_-1);
        g_cmean[bc]=mean; g_crstd[bc]=rsqrtf(var+1e-5f);
    }
}

// ---------------- kernel 2a: proj Q/K via HMMA (2-term, sgemm-style) ----------------
// Y[b][n][448] = Xt[b][n][c] * W[o][c] + bias.  CTA 256n x 64o, 8 warps 64n x 32o.
#define PJ_AH 0
#define PJ_AL 36864
#define PJ_B  73728
#define PJ_STAGE 82944
#define PJ_SMEM (2*PJ_STAGE)
__global__ __launch_bounds__(256) void proj_mma_kernel(const __half* __restrict__ Xth,
                                                       const __half* __restrict__ Xtl,
                                                       const __half* __restrict__ W16,
                                                       const float* __restrict__ bias,
                                                       __half* __restrict__ Y){
    extern __shared__ char sm[];
    uint32_t sb = smem_to_u32(sm);
    int tid=threadIdx.x, lane=tid&31, wid=tid>>5;
    int g=lane>>2, tig=lane&3;
    int wq=wid&3, wk=wid>>2;
    int lrow=lane&15, lcol=lane>>4;
    int b=blockIdx.z, n0=blockIdx.y*256, o0=blockIdx.x*64;
    const __half* Ah = Xth + ((size_t)(b*N_)+n0)*CK_;
    const __half* Al = Xtl + ((size_t)(b*N_)+n0)*CK_;

    auto issue=[&](int ch, int st){
        uint32_t base = sb + st*PJ_STAGE;
        int ck0=ch*64;
        for(int i=tid;i<2048;i+=256){
            int r=i>>3, s=i&7;
            size_t gi=(size_t)r*CK_ + ck0 + s*8;
            cp16(base+PJ_AH + r*144 + s*16, Ah + gi);
            cp16(base+PJ_AL + r*144 + s*16, Al + gi);
        }
        for(int i=tid;i<512;i+=256){
            int r=i>>3, s=i&7;
            cp16(base+PJ_B + r*144 + s*16, W16 + (size_t)(o0+r)*CK_ + ck0 + s*8);
        }
    };

    float acc[4][4][4];
    #pragma unroll
    for(int mi=0;mi<4;mi++)
        #pragma unroll
        for(int ni=0;ni<4;ni++)
            #pragma unroll
            for(int e=0;e<4;e++) acc[mi][ni][e]=0.f;

    issue(0,0); CP_COMMIT();
    for(int ch=0; ch<7; ch++){
        if(ch+1<7){ issue(ch+1,(ch+1)&1); CP_COMMIT(); CP_WAIT1(); } else { CP_WAIT0(); }
        __syncthreads();
        uint32_t stg = sb + (ch&1)*PJ_STAGE;
        #pragma unroll
        for(int ks=0;ks<4;ks++){
            int kbo = (ks*16 + lcol*8)*2;
            uint32_t bh[4][2];
            #pragma unroll
            for(int nb=0;nb<2;nb++){
                uint32_t r4[4];
                ldm4(r4, stg+PJ_B + (wk*32+nb*16+lrow)*144 + kbo);
                bh[2*nb][0]=r4[0]; bh[2*nb+1][0]=r4[1]; bh[2*nb][1]=r4[2]; bh[2*nb+1][1]=r4[3];
            }
            #pragma unroll
            for(int mi=0;mi<4;mi++){
                uint32_t ah[4], al[4];
                uint32_t off = (wq*64+mi*16+lrow)*144 + kbo;
                ldm4(ah, stg+PJ_AH + off);
                ldm4(al, stg+PJ_AL + off);
                #pragma unroll
                for(int ni=0;ni<4;ni++){
                    mma16816(acc[mi][ni], ah, bh[ni]);
                    mma16816(acc[mi][ni], al, bh[ni]);
                }
            }
        }
        __syncthreads();
    }
    #pragma unroll
    for(int mi=0;mi<4;mi++){
        int qr=wq*64+mi*16+g;
        #pragma unroll
        for(int ni=0;ni<4;ni++){
            int oc=wk*32+ni*8+tig*2;
            float2 bia=*(const float2*)&bias[o0+oc];
            __half2 h0=__floats2half2_rn(acc[mi][ni][0]+bia.x, acc[mi][ni][1]+bia.y);
            __half2 h1=__floats2half2_rn(acc[mi][ni][2]+bia.x, acc[mi][ni][3]+bia.y);
            *(__half2*)&Y[((size_t)(b*N_)+n0+qr)*CK_ + o0+oc]   = h0;
            *(__half2*)&Y[((size_t)(b*N_)+n0+qr+8)*CK_ + o0+oc] = h1;
        }
    }
}

// ---------------- kernel 2b: SIMT projection for V (v, v^2, transposed out) ----------------
template<int CIN>
__global__ __launch_bounds__(256) void projv_kernel(const float* __restrict__ X,
                                                    const float* __restrict__ W,
                                                    const float* __restrict__ bias,
                                                    __half* __restrict__ Yh){
    __shared__ float Xs[2][32*128];
    __shared__ float Ws[2][32*64];
    int b=blockIdx.z, n0=blockIdx.x*128, o0=blockIdx.y*64;
    int tid=threadIdx.x, tx=tid&15, ty=tid>>4;
    uint32_t sbX = smem_to_u32(&Xs[0][0]);
    const int nblk = CIN/32;

    auto issueX=[&](int blk, int st){
        const float* src = X + ((size_t)(b*CIN+blk*32))*N_ + n0;
        uint32_t base = sbX + st*16384;
        for(int e=tid;e<1024;e+=256){
            int cc=e>>5, s=e&31;
            cp16(base + cc*512 + s*16, src + (size_t)cc*N_ + s*4);
        }
    };
    float4 wr[2];
    auto ldW=[&](int blk){
        #pragma unroll
        for(int i=0;i<2;i++){
            int e=tid+i*256, oo=e>>3, c4=(e&7)<<2;
            wr[i] = *(const float4*)&W[(size_t)(o0+oo)*CIN + blk*32 + c4];
        }
    };
    auto stW=[&](int st){
        #pragma unroll
        for(int i=0;i<2;i++){
            int e=tid+i*256, oo=e>>3, c4=(e&7)<<2;
            Ws[st][(c4+0)*64+oo]=wr[i].x; Ws[st][(c4+1)*64+oo]=wr[i].y;
            Ws[st][(c4+2)*64+oo]=wr[i].z; Ws[st][(c4+3)*64+oo]=wr[i].w;
        }
    };

    u64v acc2[4][4];
    #pragma unroll
    for(int p=0;p<4;p++)
        #pragma unroll
        for(int j=0;j<4;j++) acc2[p][j]=0ull;

    issueX(0,0); CP_COMMIT();
    ldW(0); stW(0);
    for(int blk=0; blk<nblk; blk++){
        int cur = blk&1;
        if(blk+1<nblk){ issueX(blk+1, cur^1); CP_COMMIT(); ldW(blk+1); }
        if(blk+1<nblk) CP_WAIT1(); else CP_WAIT0();
        __syncthreads();
        if(blk+1<nblk) stW(cur^1);
        const float* Xc = &Xs[cur][0];
        const float* Wc = &Ws[cur][0];
        #pragma unroll 4
        for(int cc=0;cc<32;cc++){
            const u64v* xr=(const u64v*)&Xc[cc*128+ty*8];
            u64v x0=xr[0], x1=xr[1], x2=xr[2], x3=xr[3];
            float4 w4=*(const float4*)&Wc[cc*64+tx*4];
            u64v w0=pk2(w4.x,w4.x),w1=pk2(w4.y,w4.y),w2=pk2(w4.z,w4.z),w3=pk2(w4.w,w4.w);
            acc2[0][0]=ffma2(x0,w0,acc2[0][0]); acc2[0][1]=ffma2(x0,w1,acc2[0][1]);
            acc2[0][2]=ffma2(x0,w2,acc2[0][2]); acc2[0][3]=ffma2(x0,w3,acc2[0][3]);
            acc2[1][0]=ffma2(x1,w0,acc2[1][0]); acc2[1][1]=ffma2(x1,w1,acc2[1][1]);
            acc2[1][2]=ffma2(x1,w2,acc2[1][2]); acc2[1][3]=ffma2(x1,w3,acc2[1][3]);
            acc2[2][0]=ffma2(x2,w0,acc2[2][0]); acc2[2][1]=ffma2(x2,w1,acc2[2][1]);
            acc2[2][2]=ffma2(x2,w2,acc2[2][2]); acc2[2][3]=ffma2(x2,w3,acc2[2][3]);
            acc2[3][0]=ffma2(x3,w0,acc2[3][0]); acc2[3][1]=ffma2(x3,w1,acc2[3][1]);
            acc2[3][2]=ffma2(x3,w2,acc2[3][2]); acc2[3][3]=ffma2(x3,w3,acc2[3][3]);
        }
        __syncthreads();
    }
    float a[8][4];
    #pragma unroll
    for(int p=0;p<4;p++)
        #pragma unroll
        for(int j=0;j<4;j++) upk2(acc2[p][j],a[2*p][j],a[2*p+1][j]);
    float4 bo=*(const float4*)&bias[o0+tx*4];
    float bb[4]={bo.x,bo.y,bo.z,bo.w};
    #pragma unroll
    for(int j=0;j<4;j++){
        __align__(16) __half vh[8], wh[8];
        #pragma unroll
        for(int i=0;i<8;i++){
            float y=a[i][j]+bb[j];
            vh[i]=__float2half_rn(y);
            wh[i]=__float2half_rn(y*y);
        }
        int o=o0+tx*4+j;
        size_t rv=((size_t)b*(2*C_)+2*o)*N_+n0+ty*8;
        *(uint4*)&Yh[rv]=*(uint4*)vh; *(uint4*)&Yh[rv+N_]=*(uint4*)wh;
    }
}

// ---------------- kernel 3: S = Q K^T  (mma.sync + ldmatrix, fp32 out, 3-stage) ----------------
#define SG_Q  0
#define SG_KH 18432
#define SG_STAGE 55296
#define SG_SMEM (3*SG_STAGE)
__global__ __launch_bounds__(256) void sgemm_kernel(){
    extern __shared__ char sm[];
    uint32_t sb = smem_to_u32(sm);
    int tid=threadIdx.x, lane=tid&31, wid=tid>>5;
    int g=lane>>2, tig=lane&3;
    int wq=wid&1, wk=wid>>1;
    int lrow=lane&15, lcol=lane>>4;
    int b=blockIdx.z, q0=blockIdx.y*128, k0=blockIdx.x*256;
    const __half* Qg=g_Qh+((size_t)b*N_+q0)*CK_;
    const __half* Khg=g_Kh+((size_t)b*N_+k0)*CK_;

    auto issue=[&](int ch, int st){
        uint32_t base = sb + st*SG_STAGE;
        int ck0=ch*64;
        for(int i=tid;i<1024;i+=256){
            int r=i>>3, s=i&7;
            cp16(base+SG_Q + r*144 + s*16, Qg + (size_t)r*CK_ + ck0 + s*8);
        }
        for(int i=tid;i<2048;i+=256){
            int r=i>>3, s=i&7;
            cp16(base+SG_KH + r*144 + s*16, Khg + (size_t)r*CK_ + ck0 + s*8);
        }
    };

    float acc[4][8][4];
    #pragma unroll
    for(int mi=0;mi<4;mi++)
        #pragma unroll
        for(int ni=0;ni<8;ni++)
            #pragma unroll
            for(int e=0;e<4;e++) acc[mi][ni][e]=0.f;

    issue(0,0); CP_COMMIT();
    issue(1,1); CP_COMMIT();
    int st=2;
    for(int ch=0; ch<7; ch++){
        if(ch+2<7){ issue(ch+2,st); CP_COMMIT(); st=(st+1==3)?0:st+1; CP_WAIT2(); }
        else if(ch+1<7){ CP_WAIT1(); }
        else { CP_WAIT0(); }
        __syncthreads();
        uint32_t stg = sb + (ch%3)*SG_STAGE;
        #pragma unroll
        for(int ks=0;ks<4;ks++){
            int kbo = (ks*16 + lcol*8)*2;
            uint32_t bh[8][2];
            #pragma unroll
            for(int nb=0;nb<4;nb++){
                uint32_t r4[4];
                ldm4(r4, stg+SG_KH + (wk*64+nb*16+lrow)*144 + kbo);
                bh[2*nb][0]=r4[0]; bh[2*nb+1][0]=r4[1]; bh[2*nb][1]=r4[2]; bh[2*nb+1][1]=r4[3];
            }
            #pragma unroll
            for(int mi=0;mi<4;mi++){
                uint32_t a[4];
                ldm4(a, stg+SG_Q + (wq*64+mi*16+lrow)*144 + kbo);
                #pragma unroll
                for(int ni=0;ni<8;ni++) mma16816(acc[mi][ni], a, bh[ni]);
            }
        }
        __syncthreads();
    }
    float* So = g_S + ((size_t)b*N_+q0)*N_ + k0;
    #pragma unroll
    for(int mi=0;mi<4;mi++){
        int qr=wq*64+mi*16+g;
        #pragma unroll
        for(int ni=0;ni<8;ni++){
            int kc=wk*64+ni*8+tig*2;
            float2 v0={acc[mi][ni][0],acc[mi][ni][1]};
            float2 v1={acc[mi][ni][2],acc[mi][ni][3]};
            *(float2*)&So[(size_t)qr*N_+kc]     = v0;
            *(float2*)&So[(size_t)(qr+8)*N_+kc] = v1;
        }
    }
}

// ---------------- kernel 4: masked softmax row pass (fp32 S, fp16 P) ----------------
__global__ __launch_bounds__(256) void softmax_kernel(const int* __restrict__ cmask,
                                                      const int* __restrict__ smask){
    int b=blockIdx.y, q=blockIdx.x, tid=threadIdx.x;
    const float4* Srow=(const float4*)(g_S+((size_t)b*N_+q)*N_);
    const int4* smr=(const int4*)(smask+b*N_);
    int cm = cmask[b*N_+q]!=0;
    float s[16], mx=-3.4e38f;
    #pragma unroll
    for(int i=0;i<4;i++){
        int k4=tid+i*256;
        float4 v=Srow[k4];
        if(cm){
            int4 m=smr[k4];
            if(m.x==0)v.x=NEGV; if(m.y==0)v.y=NEGV; if(m.z==0)v.z=NEGV; if(m.w==0)v.w=NEGV;
        }
        s[4*i]=v.x;s[4*i+1]=v.y;s[4*i+2]=v.z;s[4*i+3]=v.w;
        mx=fmaxf(mx,fmaxf(fmaxf(v.x,v.y),fmaxf(v.z,v.w)));
    }
    #pragma unroll
    for(int o=16;o;o>>=1) mx=fmaxf(mx,__shfl_xor_sync(~0u,mx,o));
    __shared__ float red[8];
    int w=tid>>5,l=tid&31;
    if(l==0) red[w]=mx;
    __syncthreads();
    float M=red[0];
    #pragma unroll
    for(int i=1;i<8;i++) M=fmaxf(M,red[i]);
    __syncthreads();
    float sum=0.f;
    uint2* Prow=(uint2*)(g_P+((size_t)b*N_+q)*N_);
    #pragma unroll
    for(int i=0;i<4;i++){
        __align__(8) __half h[4];
        #pragma unroll
        for(int j=0;j<4;j++){
            float p=fast_exp(s[4*i+j]-M);
            h[j]=__float2half_rn(p);
            sum+=__half2float(h[j]);
        }
        Prow[tid+i*256]=*(uint2*)h;
    }
    #pragma unroll
    for(int o=16;o;o>>=1) sum+=__shfl_xor_sync(~0u,sum,o);
    if(l==0) red[w]=sum;
    __syncthreads();
    if(tid==0){
        float t=0.f;
        #pragma unroll
        for(int i=0;i<8;i++) t+=red[i];
        g_l[b*N_+q]=t;
    }
}

// ---------------- kernel 5: [mean,m2] = P * VT^T (mma.sync + ldmatrix) ----------------
#define PV_P 0
#define PV_V 18432
#define PV_STAGE 55296
#define PV_SMEM (3*PV_STAGE)
__global__ __launch_bounds__(256) void pv_kernel(){
    extern __shared__ char sm[];
    uint32_t sb = smem_to_u32(sm);
    int tid=threadIdx.x, lane=tid&31, wid=tid>>5;
    int g=lane>>2, tig=lane&3;
    int wq=wid&1, wk=wid>>1;
    int lrow=lane&15, lcol=lane>>4;
    int b=blockIdx.z, q0=blockIdx.y*128, j0=blockIdx.x*256;
    const __half* Pg = g_P  + ((size_t)b*N_+q0)*N_;
    const __half* Vg = g_VTh+ ((size_t)b*2*C_+j0)*N_;

    auto issue=[&](int ch, int st){
        uint32_t base = sb + st*PV_STAGE;
        int kk0=ch*64;
        for(int i=tid;i<1024;i+=256){
            int r=i>>3, s=i&7;
            cp16(base+PV_P + r*144 + s*16, Pg + (size_t)r*N_ + kk0 + s*8);
        }
        for(int i=tid;i<2048;i+=256){
            int r=i>>3, s=i&7;
            cp16(base+PV_V + r*144 + s*16, Vg + (size_t)r*N_ + kk0 + s*8);
        }
    };

    float acc[4][8][4];
    #pragma unroll
    for(int mi=0;mi<4;mi++)
        #pragma unroll
        for(int ni=0;ni<8;ni++)
            #pragma unroll
            for(int e=0;e<4;e++) acc[mi][ni][e]=0.f;

    issue(0,0); CP_COMMIT();
    issue(1,1); CP_COMMIT();
    int st=2;
    for(int ch=0; ch<64; ch++){
        if(ch+2<64){ issue(ch+2,st); CP_COMMIT(); st=(st+1==3)?0:st+1; CP_WAIT2(); }
        else if(ch+1<64){ CP_WAIT1(); }
        else { CP_WAIT0(); }
        __syncthreads();
        uint32_t stg = sb + (ch%3)*PV_STAGE;
        #pragma unroll
        for(int ks=0;ks<4;ks++){
            int kbo = (ks*16 + lcol*8)*2;
            uint32_t bh[8][2];
            #pragma unroll
            for(int nb=0;nb<4;nb++){
                uint32_t r4[4];
                ldm4(r4, stg+PV_V + (wk*64+nb*16+lrow)*144 + kbo);
                bh[2*nb][0]=r4[0]; bh[2*nb+1][0]=r4[1]; bh[2*nb][1]=r4[2]; bh[2*nb+1][1]=r4[3];
            }
            #pragma unroll
            for(int mi=0;mi<4;mi++){
                uint32_t a[4];
                ldm4(a, stg+PV_P + (wq*64+mi*16+lrow)*144 + kbo);
                #pragma unroll
                for(int ni=0;ni<8;ni++) mma16816(acc[mi][ni], a, bh[ni]);
            }
        }
        __syncthreads();
    }
    float* Ob = g_O + ((size_t)b*N_+q0)*(2*C_) + j0;
    #pragma unroll
    for(int mi=0;mi<4;mi++){
        int qr=wq*64+mi*16+g;
        #pragma unroll
        for(int ni=0;ni<8;ni++){
            int jc=wk*64+ni*8+tig*2;
            float2 v0={acc[mi][ni][0],acc[mi][ni][1]};
            float2 v1={acc[mi][ni][2],acc[mi][ni][3]};
            *(float2*)&Ob[(size_t)qr*(2*C_)+jc]     = v0;
            *(float2*)&Ob[(size_t)(qr+8)*(2*C_)+jc] = v1;
        }
    }
}

// ---------------- kernel 6: finalize ----------------
__global__ __launch_bounds__(256) void final_kernel(const float* __restrict__ content,
                                                    float* __restrict__ out){
    int b=blockIdx.z, c=blockIdx.y;
    int n=(blockIdx.x*256+threadIdx.x)*4;
    const float* Ob=g_O+(size_t)b*N_*(2*C_);
    float4 l4=*(const float4*)&g_l[b*N_+n];
    float lv[4]={l4.x,l4.y,l4.z,l4.w};
    float cmv=g_cmean[b*C_+c], cr=g_crstd[b*C_+c];
    size_t oi=((size_t)(b*C_+c))*N_+n;
    float4 cx=*(const float4*)&content[oi];
    float ci[4]={cx.x,cx.y,cx.z,cx.w};
    float res[4];
    #pragma unroll
    for(int i=0;i<4;i++){
        float2 mv=*(const float2*)&Ob[(size_t)(n+i)*(2*C_)+2*c];
        float inv=1.0f/lv[i];
        float mean=mv.x*inv, m2=mv.y*inv;
        float sd=sqrtf(fmaxf(m2-mean*mean,0.f));
        res[i]=sd*(ci[i]-cmv)*cr+mean;
    }
    float4 ro={res[0],res[1],res[2],res[3]};
    *(float4*)&out[oi]=ro;
}

// ---------------- launch ----------------
extern "C" void kernel_launch(void* const* d_in, const int* in_sizes, int n_in,
                              void* d_out, int out_size){
    const float* content     = (const float*)d_in[0];
    const float* style       = (const float*)d_in[1];
    const float* content_key = (const float*)d_in[2];
    const float* style_key   = (const float*)d_in[3];
    const int*   cmask       = (const int*)d_in[4];
    const int*   smask       = (const int*)d_in[5];
    const float* Wf=(const float*)d_in[6];  const float* bf=(const float*)d_in[7];
    const float* Wg=(const float*)d_in[8];  const float* bg=(const float*)d_in[9];
    const float* Wh=(const float*)d_in[10]; const float* bh=(const float*)d_in[11];
    float* out=(float*)d_out;

    __half *qh,*kh,*vth,*cth,*ctl,*sth,*stl,*wf16,*wg16;
    cudaGetSymbolAddress((void**)&qh,  g_Qh);
    cudaGetSymbolAddress((void**)&kh,  g_Kh);
    cudaGetSymbolAddress((void**)&vth, g_VTh);
    cudaGetSymbolAddress((void**)&cth, g_CTh); cudaGetSymbolAddress((void**)&ctl, g_CTl);
    cudaGetSymbolAddress((void**)&sth, g_STh); cudaGetSymbolAddress((void**)&stl, g_STl);
    cudaGetSymbolAddress((void**)&wf16, g_Wf16); cudaGetSymbolAddress((void**)&wg16, g_Wg16);
    cudaFuncSetAttribute(proj_mma_kernel, cudaFuncAttributeMaxDynamicSharedMemorySize, PJ_SMEM);
    cudaFuncSetAttribute(sgemm_kernel, cudaFuncAttributeMaxDynamicSharedMemorySize, SG_SMEM);
    cudaFuncSetAttribute(pv_kernel,    cudaFuncAttributeMaxDynamicSharedMemorySize, PV_SMEM);

    int nw4 = CK_*CK_/4;
    stats_kernel<<<B_*C_, 256>>>(content);
    transpose_kernel<<<dim3(128, 14, B_), 256>>>(content_key, cth, ctl);
    transpose_kernel<<<dim3(128, 14, B_), 256>>>(style_key,   sth, stl);
    whalf_kernel<<<(nw4+255)/256, 256>>>(Wf, wf16, nw4);
    whalf_kernel<<<(nw4+255)/256, 256>>>(Wg, wg16, nw4);
    proj_mma_kernel<<<dim3(7, 16, B_), 256, PJ_SMEM>>>(cth, ctl, wf16, bf, qh);
    proj_mma_kernel<<<dim3(7, 16, B_), 256, PJ_SMEM>>>(sth, stl, wg16, bg, kh);
    projv_kernel<C_><<<dim3(32, 4, B_), 256>>>(style, Wh, bh, vth);
    sgemm_kernel<<<dim3(16, 32, B_), 256, SG_SMEM>>>();
    softmax_kernel<<<dim3(N_, B_), 256>>>(cmask, smask);
    pv_kernel<<<dim3(2, 32, B_), 256, PV_SMEM>>>();
    final_kernel<<<dim3(4, C_, B_), 256>>>(content, out);
}

// round 11
// speedup vs baseline: 1.6075x; 1.0396x over previous
#include <cuda_runtime.h>
#include <cuda_fp16.h>
#include <cstdint>

#define B_   4
#define C_   256
#define CK_  448
#define N_   4096
#define NEGV (-1e15f)

// ---------------- device scratch ----------------
__device__ __half g_Qh[(size_t)B_*N_*CK_];
__device__ __half g_Kh[(size_t)B_*N_*CK_];
__device__ __half g_VTh[(size_t)B_*2*C_*N_];   // [b][j][n], j=2c:v, 2c+1:v^2
__device__ float  g_S[(size_t)B_*N_*N_];       // [b][q][k] fp32 scores
__device__ __half g_P[(size_t)B_*N_*N_];       // [b][q][k]
__device__ float  g_l[B_*N_];
__device__ float  g_O[(size_t)B_*N_*2*C_];     // [b][q][j]
__device__ float  g_cmean[B_*C_], g_crstd[B_*C_];
__device__ float  g_addm[B_*N_];               // additive key mask
// transposed fp16 hi/lo inputs: [b][n][c]
__device__ __half g_CTh[(size_t)B_*N_*CK_], g_CTl[(size_t)B_*N_*CK_];
__device__ __half g_STh[(size_t)B_*N_*CK_], g_STl[(size_t)B_*N_*CK_];
__device__ __half g_SVh[(size_t)B_*N_*C_],  g_SVl[(size_t)B_*N_*C_];
__device__ __half g_Wf16[CK_*CK_], g_Wg16[CK_*CK_];
__device__ __half g_Whh[C_*C_],    g_Whl[C_*C_];

// ---------------- mma.sync / ldmatrix / cp.async ----------------
__device__ __forceinline__ uint32_t smem_to_u32(const void*p){
    uint32_t a;asm("{ .reg .u64 t; cvta.to.shared.u64 t, %1; cvt.u32.u64 %0, t; }":"=r"(a):"l"(p));return a;}
__device__ __forceinline__ void mma16816(float* c, const uint32_t* a, const uint32_t* b){
    asm volatile("mma.sync.aligned.m16n8k16.row.col.f32.f16.f16.f32 "
        "{%0,%1,%2,%3}, {%4,%5,%6,%7}, {%8,%9}, {%0,%1,%2,%3};"
        : "+f"(c[0]),"+f"(c[1]),"+f"(c[2]),"+f"(c[3])
        : "r"(a[0]),"r"(a[1]),"r"(a[2]),"r"(a[3]), "r"(b[0]),"r"(b[1]));
}
__device__ __forceinline__ void ldm4(uint32_t* r, uint32_t addr){
    asm volatile("ldmatrix.sync.aligned.m8n8.x4.shared.b16 {%0,%1,%2,%3}, [%4];"
        :"=r"(r[0]),"=r"(r[1]),"=r"(r[2]),"=r"(r[3]):"r"(addr));
}
__device__ __forceinline__ void cp16(uint32_t dst, const void* src){
    asm volatile("cp.async.cg.shared.global [%0], [%1], 16;" :: "r"(dst), "l"(src));
}
#define CP_COMMIT() asm volatile("cp.async.commit_group;" ::: "memory")
#define CP_WAIT2()  asm volatile("cp.async.wait_group 2;" ::: "memory")
#define CP_WAIT1()  asm volatile("cp.async.wait_group 1;" ::: "memory")
#define CP_WAIT0()  asm volatile("cp.async.wait_group 0;" ::: "memory")

// ---------------- fast exp on fma pipe ----------------
__device__ __forceinline__ float fast_exp(float x){
    float t = fmaxf(x * 1.4426950408889634f, -126.0f);
    float fi = t + 12582912.0f;
    int i = __float_as_int(fi) - 0x4B400000;
    float f = t - (fi - 12582912.0f);
    float p = 1.5424236e-4f;
    p = fmaf(p,f,1.3333558e-3f); p = fmaf(p,f,9.6181291e-3f);
    p = fmaf(p,f,5.5504109e-2f); p = fmaf(p,f,2.4022651e-1f);
    p = fmaf(p,f,6.9314718e-1f); p = fmaf(p,f,1.0f);
    return __int_as_float(__float_as_int(p) + (i<<23));
}
__device__ __forceinline__ void hsplit(float y, __half& h, __half& l){
    h = __float2half_rn(y); l = __float2half_rn(y - __half2float(h));
}

// ---------------- megaprep: stats + transposes + weight converts + mask ----------------
#define MPB_STATS 0
#define MPB_TCK1  1024
#define MPB_TCK2  (MPB_TCK1+7168)
#define MPB_TC    (MPB_TCK2+7168)
#define MPB_WF    (MPB_TC+4096)
#define MPB_WG    (MPB_WF+196)
#define MPB_WHS   (MPB_WG+196)
#define MPB_MSK   (MPB_WHS+64)
#define MP_BLOCKS (MPB_MSK+64)

__device__ void dev_transpose(const float* __restrict__ X, __half* __restrict__ Th,
                              __half* __restrict__ Tl, int CIN, int t, float (*ts)[33]){
    int cper = CIN/32;
    int nb = t & 127, cb = (t>>7) % cper, b = t/(128*cper);
    int n0 = nb*32, c0 = cb*32;
    int tid=threadIdx.x, nl=tid&31, cw=tid>>5;
    #pragma unroll
    for(int i=0;i<4;i++){
        int c=cw+i*8;
        ts[c][nl]=X[((size_t)b*CIN + c0+c)*N_ + n0+nl];
    }
    __syncthreads();
    int n=tid>>3, c4=(tid&7)*4;
    __align__(8) __half hh[4], hl[4];
    #pragma unroll
    for(int j=0;j<4;j++) hsplit(ts[c4+j][n], hh[j], hl[j]);
    size_t o=((size_t)b*N_ + n0+n)*CIN + c0+c4;
    *(uint2*)&Th[o]=*(uint2*)hh;
    *(uint2*)&Tl[o]=*(uint2*)hl;
}

__global__ __launch_bounds__(256) void megaprep_kernel(const float* __restrict__ content,
        const float* __restrict__ content_key, const float* __restrict__ style_key,
        const float* __restrict__ style, const int* __restrict__ smask,
        const float* __restrict__ Wf, const float* __restrict__ Wg,
        const float* __restrict__ Wh){
    __shared__ float ts[32][33];
    __shared__ float r1[8], r2[8];
    int bid=blockIdx.x, tid=threadIdx.x;
    if(bid < MPB_TCK1){
        // content stats, bc = bid
        int bc=bid;
        const float4* x = (const float4*)(content + (size_t)bc*N_);
        float s=0.f,q=0.f;
        for(int i=tid;i<N_/4;i+=256){float4 v=x[i];s+=v.x+v.y+v.z+v.w;q+=v.x*v.x+v.y*v.y+v.z*v.z+v.w*v.w;}
        #pragma unroll
        for(int o=16;o;o>>=1){s+=__shfl_xor_sync(~0u,s,o);q+=__shfl_xor_sync(~0u,q,o);}
        int w=tid>>5,l=tid&31;
        if(l==0){r1[w]=s;r2[w]=q;}
        __syncthreads();
        if(tid==0){
            float S=0,Q=0;
            #pragma unroll
            for(int i=0;i<8;i++){S+=r1[i];Q+=r2[i];}
            float mean=S/(float)N_;
            float var=(Q-(float)N_*mean*mean)/(float)(N_-1);
            g_cmean[bc]=mean; g_crstd[bc]=rsqrtf(var+1e-5f);
        }
    } else if(bid < MPB_TCK2){
        dev_transpose(content_key, g_CTh, g_CTl, CK_, bid-MPB_TCK1, ts);
    } else if(bid < MPB_TC){
        dev_transpose(style_key, g_STh, g_STl, CK_, bid-MPB_TCK2, ts);
    } else if(bid < MPB_WF){
        dev_transpose(style, g_SVh, g_SVl, C_, bid-MPB_TC, ts);
    } else if(bid < MPB_WG){
        int i=(bid-MPB_WF)*256+tid;
        float4 v=((const float4*)Wf)[i];
        __align__(8) __half h[4];
        h[0]=__float2half_rn(v.x); h[1]=__float2half_rn(v.y);
        h[2]=__float2half_rn(v.z); h[3]=__float2half_rn(v.w);
        ((uint2*)g_Wf16)[i]=*(uint2*)h;
    } else if(bid < MPB_WHS){
        int i=(bid-MPB_WG)*256+tid;
        float4 v=((const float4*)Wg)[i];
        __align__(8) __half h[4];
        h[0]=__float2half_rn(v.x); h[1]=__float2half_rn(v.y);
        h[2]=__float2half_rn(v.z); h[3]=__float2half_rn(v.w);
        ((uint2*)g_Wg16)[i]=*(uint2*)h;
    } else if(bid < MPB_MSK){
        int i=(bid-MPB_WHS)*256+tid;
        float4 v=((const float4*)Wh)[i];
        __align__(8) __half hh[4], hl[4];
        float vv[4]={v.x,v.y,v.z,v.w};
        #pragma unroll
        for(int j=0;j<4;j++) hsplit(vv[j],hh[j],hl[j]);
        ((uint2*)g_Whh)[i]=*(uint2*)hh;
        ((uint2*)g_Whl)[i]=*(uint2*)hl;
    } else {
        int i=(bid-MPB_MSK)*256+tid;
        g_addm[i] = smask[i] ? 0.f : NEGV;
    }
}

// ---------------- proj Q/K via HMMA (2-term, validated) ----------------
#define PJ_AH 0
#define PJ_AL 36864
#define PJ_B  73728
#define PJ_STAGE 82944
#define PJ_SMEM (2*PJ_STAGE)
__global__ __launch_bounds__(256) void proj_mma_kernel(const __half* __restrict__ Xth,
                                                       const __half* __restrict__ Xtl,
                                                       const __half* __restrict__ W16,
                                                       const float* __restrict__ bias,
                                                       __half* __restrict__ Y){
    extern __shared__ char sm[];
    uint32_t sb = smem_to_u32(sm);
    int tid=threadIdx.x, lane=tid&31, wid=tid>>5;
    int g=lane>>2, tig=lane&3;
    int wq=wid&3, wk=wid>>2;
    int lrow=lane&15, lcol=lane>>4;
    int b=blockIdx.z, n0=blockIdx.y*256, o0=blockIdx.x*64;
    const __half* Ah = Xth + ((size_t)(b*N_)+n0)*CK_;
    const __half* Al = Xtl + ((size_t)(b*N_)+n0)*CK_;

    auto issue=[&](int ch, int st){
        uint32_t base = sb + st*PJ_STAGE;
        int ck0=ch*64;
        for(int i=tid;i<2048;i+=256){
            int r=i>>3, s=i&7;
            size_t gi=(size_t)r*CK_ + ck0 + s*8;
            cp16(base+PJ_AH + r*144 + s*16, Ah + gi);
            cp16(base+PJ_AL + r*144 + s*16, Al + gi);
        }
        for(int i=tid;i<512;i+=256){
            int r=i>>3, s=i&7;
            cp16(base+PJ_B + r*144 + s*16, W16 + (size_t)(o0+r)*CK_ + ck0 + s*8);
        }
    };

    float acc[4][4][4];
    #pragma unroll
    for(int mi=0;mi<4;mi++)
        #pragma unroll
        for(int ni=0;ni<4;ni++)
            #pragma unroll
            for(int e=0;e<4;e++) acc[mi][ni][e]=0.f;

    issue(0,0); CP_COMMIT();
    for(int ch=0; ch<7; ch++){
        if(ch+1<7){ issue(ch+1,(ch+1)&1); CP_COMMIT(); CP_WAIT1(); } else { CP_WAIT0(); }
        __syncthreads();
        uint32_t stg = sb + (ch&1)*PJ_STAGE;
        #pragma unroll
        for(int ks=0;ks<4;ks++){
            int kbo = (ks*16 + lcol*8)*2;
            uint32_t bh[4][2];
            #pragma unroll
            for(int nb=0;nb<2;nb++){
                uint32_t r4[4];
                ldm4(r4, stg+PJ_B + (wk*32+nb*16+lrow)*144 + kbo);
                bh[2*nb][0]=r4[0]; bh[2*nb+1][0]=r4[1]; bh[2*nb][1]=r4[2]; bh[2*nb+1][1]=r4[3];
            }
            #pragma unroll
            for(int mi=0;mi<4;mi++){
                uint32_t ah[4], al[4];
                uint32_t off = (wq*64+mi*16+lrow)*144 + kbo;
                ldm4(ah, stg+PJ_AH + off);
                ldm4(al, stg+PJ_AL + off);
                #pragma unroll
                for(int ni=0;ni<4;ni++){
                    mma16816(acc[mi][ni], ah, bh[ni]);
                    mma16816(acc[mi][ni], al, bh[ni]);
                }
            }
        }
        __syncthreads();
    }
    #pragma unroll
    for(int mi=0;mi<4;mi++){
        int qr=wq*64+mi*16+g;
        #pragma unroll
        for(int ni=0;ni<4;ni++){
            int oc=wk*32+ni*8+tig*2;
            float2 bia=*(const float2*)&bias[o0+oc];
            __half2 h0=__floats2half2_rn(acc[mi][ni][0]+bia.x, acc[mi][ni][1]+bia.y);
            __half2 h1=__floats2half2_rn(acc[mi][ni][2]+bia.x, acc[mi][ni][3]+bia.y);
            *(__half2*)&Y[((size_t)(b*N_)+n0+qr)*CK_ + o0+oc]   = h0;
            *(__half2*)&Y[((size_t)(b*N_)+n0+qr+8)*CK_ + o0+oc] = h1;
        }
    }
}

// ---------------- projV via HMMA (3-term, v & v^2 epilogue) ----------------
#define VJ_AH 0
#define VJ_AL 36864
#define VJ_BH 73728
#define VJ_BL 82944
#define VJ_STAGE 92160
#define VJ_SMEM (2*VJ_STAGE)
__global__ __launch_bounds__(256) void projv_mma_kernel(const float* __restrict__ bias){
    extern __shared__ char sm[];
    uint32_t sb = smem_to_u32(sm);
    int tid=threadIdx.x, lane=tid&31, wid=tid>>5;
    int g=lane>>2, tig=lane&3;
    int wq=wid&3, wk=wid>>2;
    int lrow=lane&15, lcol=lane>>4;
    int b=blockIdx.z, n0=blockIdx.y*256, o0=blockIdx.x*64;
    const __half* Ah = g_SVh + ((size_t)(b*N_)+n0)*C_;
    const __half* Al = g_SVl + ((size_t)(b*N_)+n0)*C_;

    auto issue=[&](int ch, int st){
        uint32_t base = sb + st*VJ_STAGE;
        int ck0=ch*64;
        for(int i=tid;i<2048;i+=256){
            int r=i>>3, s=i&7;
            size_t gi=(size_t)r*C_ + ck0 + s*8;
            cp16(base+VJ_AH + r*144 + s*16, Ah + gi);
            cp16(base+VJ_AL + r*144 + s*16, Al + gi);
        }
        for(int i=tid;i<512;i+=256){
            int r=i>>3, s=i&7;
            size_t gi=(size_t)(o0+r)*C_ + ck0 + s*8;
            cp16(base+VJ_BH + r*144 + s*16, g_Whh + gi);
            cp16(base+VJ_BL + r*144 + s*16, g_Whl + gi);
        }
    };

    float acc[4][4][4];
    #pragma unroll
    for(int mi=0;mi<4;mi++)
        #pragma unroll
        for(int ni=0;ni<4;ni++)
            #pragma unroll
            for(int e=0;e<4;e++) acc[mi][ni][e]=0.f;

    issue(0,0); CP_COMMIT();
    for(int ch=0; ch<4; ch++){
        if(ch+1<4){ issue(ch+1,(ch+1)&1); CP_COMMIT(); CP_WAIT1(); } else { CP_WAIT0(); }
        __syncthreads();
        uint32_t stg = sb + (ch&1)*VJ_STAGE;
        #pragma unroll
        for(int ks=0;ks<4;ks++){
            int kbo = (ks*16 + lcol*8)*2;
            uint32_t bh[4][2], bl[4][2];
            #pragma unroll
            for(int nb=0;nb<2;nb++){
                uint32_t r4[4];
                uint32_t off = (wk*32+nb*16+lrow)*144 + kbo;
                ldm4(r4, stg+VJ_BH + off);
                bh[2*nb][0]=r4[0]; bh[2*nb+1][0]=r4[1]; bh[2*nb][1]=r4[2]; bh[2*nb+1][1]=r4[3];
                ldm4(r4, stg+VJ_BL + off);
                bl[2*nb][0]=r4[0]; bl[2*nb+1][0]=r4[1]; bl[2*nb][1]=r4[2]; bl[2*nb+1][1]=r4[3];
            }
            #pragma unroll
            for(int mi=0;mi<4;mi++){
                uint32_t ah[4], al[4];
                uint32_t off = (wq*64+mi*16+lrow)*144 + kbo;
                ldm4(ah, stg+VJ_AH + off);
                ldm4(al, stg+VJ_AL + off);
                #pragma unroll
                for(int ni=0;ni<4;ni++){
                    mma16816(acc[mi][ni], ah, bh[ni]);
                    mma16816(acc[mi][ni], ah, bl[ni]);
                    mma16816(acc[mi][ni], al, bh[ni]);
                }
            }
        }
        __syncthreads();
    }
    // epilogue: y, y^2 -> smem [128j][264n] -> coalesced VT store
    __half* ep = (__half*)sm;
    #pragma unroll
    for(int mi=0;mi<4;mi++){
        int qr=wq*64+mi*16+g;
        #pragma unroll
        for(int ni=0;ni<4;ni++){
            int oc=wk*32+ni*8+tig*2;
            float2 bia=*(const float2*)&bias[o0+oc];
            float y00=acc[mi][ni][0]+bia.x, y01=acc[mi][ni][1]+bia.y;
            float y10=acc[mi][ni][2]+bia.x, y11=acc[mi][ni][3]+bia.y;
            ep[(2*oc+0)*264+qr]   = __float2half_rn(y00);
            ep[(2*oc+1)*264+qr]   = __float2half_rn(y00*y00);
            ep[(2*oc+2)*264+qr]   = __float2half_rn(y01);
            ep[(2*oc+3)*264+qr]   = __float2half_rn(y01*y01);
            ep[(2*oc+0)*264+qr+8] = __float2half_rn(y10);
            ep[(2*oc+1)*264+qr+8] = __float2half_rn(y10*y10);
            ep[(2*oc+2)*264+qr+8] = __float2half_rn(y11);
            ep[(2*oc+3)*264+qr+8] = __float2half_rn(y11*y11);
        }
    }
    __syncthreads();
    __half* VTo = g_VTh + ((size_t)b*(2*C_) + 2*o0)*N_ + n0;
    for(int e=tid;e<4096;e+=256){
        int r=e>>5, c=(e&31)*8;
        *(uint4*)&VTo[(size_t)r*N_ + c] = *(uint4*)&ep[r*264 + c];
    }
}

// ---------------- sgemm: S = Q K^T  (mma.sync + ldmatrix, fp32 out, 3-stage) ----------------
#define SG_Q  0
#define SG_KH 18432
#define SG_STAGE 55296
#define SG_SMEM (3*SG_STAGE)
__global__ __launch_bounds__(256) void sgemm_kernel(){
    extern __shared__ char sm[];
    uint32_t sb = smem_to_u32(sm);
    int tid=threadIdx.x, lane=tid&31, wid=tid>>5;
    int g=lane>>2, tig=lane&3;
    int wq=wid&1, wk=wid>>1;
    int lrow=lane&15, lcol=lane>>4;
    int b=blockIdx.z, q0=blockIdx.y*128, k0=blockIdx.x*256;
    const __half* Qg=g_Qh+((size_t)b*N_+q0)*CK_;
    const __half* Khg=g_Kh+((size_t)b*N_+k0)*CK_;

    auto issue=[&](int ch, int st){
        uint32_t base = sb + st*SG_STAGE;
        int ck0=ch*64;
        for(int i=tid;i<1024;i+=256){
            int r=i>>3, s=i&7;
            cp16(base+SG_Q + r*144 + s*16, Qg + (size_t)r*CK_ + ck0 + s*8);
        }
        for(int i=tid;i<2048;i+=256){
            int r=i>>3, s=i&7;
            cp16(base+SG_KH + r*144 + s*16, Khg + (size_t)r*CK_ + ck0 + s*8);
        }
    };

    float acc[4][8][4];
    #pragma unroll
    for(int mi=0;mi<4;mi++)
        #pragma unroll
        for(int ni=0;ni<8;ni++)
            #pragma unroll
            for(int e=0;e<4;e++) acc[mi][ni][e]=0.f;

    issue(0,0); CP_COMMIT();
    issue(1,1); CP_COMMIT();
    int st=2;
    for(int ch=0; ch<7; ch++){
        if(ch+2<7){ issue(ch+2,st); CP_COMMIT(); st=(st+1==3)?0:st+1; CP_WAIT2(); }
        else if(ch+1<7){ CP_WAIT1(); }
        else { CP_WAIT0(); }
        __syncthreads();
        uint32_t stg = sb + (ch%3)*SG_STAGE;
        #pragma unroll
        for(int ks=0;ks<4;ks++){
            int kbo = (ks*16 + lcol*8)*2;
            uint32_t bh[8][2];
            #pragma unroll
            for(int nb=0;nb<4;nb++){
                uint32_t r4[4];
                ldm4(r4, stg+SG_KH + (wk*64+nb*16+lrow)*144 + kbo);
                bh[2*nb][0]=r4[0]; bh[2*nb+1][0]=r4[1]; bh[2*nb][1]=r4[2]; bh[2*nb+1][1]=r4[3];
            }
            #pragma unroll
            for(int mi=0;mi<4;mi++){
                uint32_t a[4];
                ldm4(a, stg+SG_Q + (wq*64+mi*16+lrow)*144 + kbo);
                #pragma unroll
                for(int ni=0;ni<8;ni++) mma16816(acc[mi][ni], a, bh[ni]);
            }
        }
        __syncthreads();
    }
    float* So = g_S + ((size_t)b*N_+q0)*N_ + k0;
    #pragma unroll
    for(int mi=0;mi<4;mi++){
        int qr=wq*64+mi*16+g;
        #pragma unroll
        for(int ni=0;ni<8;ni++){
            int kc=wk*64+ni*8+tig*2;
            float2 v0={acc[mi][ni][0],acc[mi][ni][1]};
            float2 v1={acc[mi][ni][2],acc[mi][ni][3]};
            *(float2*)&So[(size_t)qr*N_+kc]     = v0;
            *(float2*)&So[(size_t)(qr+8)*N_+kc] = v1;
        }
    }
}

// ---------------- softmax (additive mask vector, fp32 S, fp16 P) ----------------
__global__ __launch_bounds__(256) void softmax_kernel(const int* __restrict__ cmask){
    int b=blockIdx.y, q=blockIdx.x, tid=threadIdx.x;
    const float4* Srow=(const float4*)(g_S+((size_t)b*N_+q)*N_);
    const float4* Am=(const float4*)(g_addm + b*N_);
    float cmf = (cmask[b*N_+q]!=0) ? 1.f : 0.f;
    float s[16], mx=-3.4e38f;
    #pragma unroll
    for(int i=0;i<4;i++){
        int k4=tid+i*256;
        float4 v=Srow[k4];
        float4 a=Am[k4];
        v.x=fmaf(cmf,a.x,v.x); v.y=fmaf(cmf,a.y,v.y);
        v.z=fmaf(cmf,a.z,v.z); v.w=fmaf(cmf,a.w,v.w);
        s[4*i]=v.x;s[4*i+1]=v.y;s[4*i+2]=v.z;s[4*i+3]=v.w;
        mx=fmaxf(mx,fmaxf(fmaxf(v.x,v.y),fmaxf(v.z,v.w)));
    }
    #pragma unroll
    for(int o=16;o;o>>=1) mx=fmaxf(mx,__shfl_xor_sync(~0u,mx,o));
    __shared__ float red[8];
    int w=tid>>5,l=tid&31;
    if(l==0) red[w]=mx;
    __syncthreads();
    float M=red[0];
    #pragma unroll
    for(int i=1;i<8;i++) M=fmaxf(M,red[i]);
    __syncthreads();
    float sum=0.f;
    uint2* Prow=(uint2*)(g_P+((size_t)b*N_+q)*N_);
    #pragma unroll
    for(int i=0;i<4;i++){
        __align__(8) __half h[4];
        #pragma unroll
        for(int j=0;j<4;j++){
            float p=fast_exp(s[4*i+j]-M);
            h[j]=__float2half_rn(p);
            sum+=__half2float(h[j]);
        }
        Prow[tid+i*256]=*(uint2*)h;
    }
    #pragma unroll
    for(int o=16;o;o>>=1) sum+=__shfl_xor_sync(~0u,sum,o);
    if(l==0) red[w]=sum;
    __syncthreads();
    if(tid==0){
        float t=0.f;
        #pragma unroll
        for(int i=0;i<8;i++) t+=red[i];
        g_l[b*N_+q]=t;
    }
}

// ---------------- pv: [mean,m2] = P * VT^T ----------------
#define PV_P 0
#define PV_V 18432
#define PV_STAGE 55296
#define PV_SMEM (3*PV_STAGE)
__global__ __launch_bounds__(256) void pv_kernel(){
    extern __shared__ char sm[];
    uint32_t sb = smem_to_u32(sm);
    int tid=threadIdx.x, lane=tid&31, wid=tid>>5;
    int g=lane>>2, tig=lane&3;
    int wq=wid&1, wk=wid>>1;
    int lrow=lane&15, lcol=lane>>4;
    int b=blockIdx.z, q0=blockIdx.y*128, j0=blockIdx.x*256;
    const __half* Pg = g_P  + ((size_t)b*N_+q0)*N_;
    const __half* Vg = g_VTh+ ((size_t)b*2*C_+j0)*N_;

    auto issue=[&](int ch, int st){
        uint32_t base = sb + st*PV_STAGE;
        int kk0=ch*64;
        for(int i=tid;i<1024;i+=256){
            int r=i>>3, s=i&7;
            cp16(base+PV_P + r*144 + s*16, Pg + (size_t)r*N_ + kk0 + s*8);
        }
        for(int i=tid;i<2048;i+=256){
            int r=i>>3, s=i&7;
            cp16(base+PV_V + r*144 + s*16, Vg + (size_t)r*N_ + kk0 + s*8);
        }
    };

    float acc[4][8][4];
    #pragma unroll
    for(int mi=0;mi<4;mi++)
        #pragma unroll
        for(int ni=0;ni<8;ni++)
            #pragma unroll
            for(int e=0;e<4;e++) acc[mi][ni][e]=0.f;

    issue(0,0); CP_COMMIT();
    issue(1,1); CP_COMMIT();
    int st=2;
    for(int ch=0; ch<64; ch++){
        if(ch+2<64){ issue(ch+2,st); CP_COMMIT(); st=(st+1==3)?0:st+1; CP_WAIT2(); }
        else if(ch+1<64){ CP_WAIT1(); }
        else { CP_WAIT0(); }
        __syncthreads();
        uint32_t stg = sb + (ch%3)*PV_STAGE;
        #pragma unroll
        for(int ks=0;ks<4;ks++){
            int kbo = (ks*16 + lcol*8)*2;
            uint32_t bh[8][2];
            #pragma unroll
            for(int nb=0;nb<4;nb++){
                uint32_t r4[4];
                ldm4(r4, stg+PV_V + (wk*64+nb*16+lrow)*144 + kbo);
                bh[2*nb][0]=r4[0]; bh[2*nb+1][0]=r4[1]; bh[2*nb][1]=r4[2]; bh[2*nb+1][1]=r4[3];
            }
            #pragma unroll
            for(int mi=0;mi<4;mi++){
                uint32_t a[4];
                ldm4(a, stg+PV_P + (wq*64+mi*16+lrow)*144 + kbo);
                #pragma unroll
                for(int ni=0;ni<8;ni++) mma16816(acc[mi][ni], a, bh[ni]);
            }
        }
        __syncthreads();
    }
    float* Ob = g_O + ((size_t)b*N_+q0)*(2*C_) + j0;
    #pragma unroll
    for(int mi=0;mi<4;mi++){
        int qr=wq*64+mi*16+g;
        #pragma unroll
        for(int ni=0;ni<8;ni++){
            int jc=wk*64+ni*8+tig*2;
            float2 v0={acc[mi][ni][0],acc[mi][ni][1]};
            float2 v1={acc[mi][ni][2],acc[mi][ni][3]};
            *(float2*)&Ob[(size_t)qr*(2*C_)+jc]     = v0;
            *(float2*)&Ob[(size_t)(qr+8)*(2*C_)+jc] = v1;
        }
    }
}

// ---------------- finalize ----------------
__global__ __launch_bounds__(256) void final_kernel(const float* __restrict__ content,
                                                    float* __restrict__ out){
    int b=blockIdx.z, c=blockIdx.y;
    int n=(blockIdx.x*256+threadIdx.x)*4;
    const float* Ob=g_O+(size_t)b*N_*(2*C_);
    float4 l4=*(const float4*)&g_l[b*N_+n];
    float lv[4]={l4.x,l4.y,l4.z,l4.w};
    float cmv=g_cmean[b*C_+c], cr=g_crstd[b*C_+c];
    size_t oi=((size_t)(b*C_+c))*N_+n;
    float4 cx=*(const float4*)&content[oi];
    float ci[4]={cx.x,cx.y,cx.z,cx.w};
    float res[4];
    #pragma unroll
    for(int i=0;i<4;i++){
        float2 mv=*(const float2*)&Ob[(size_t)(n+i)*(2*C_)+2*c];
        float inv=1.0f/lv[i];
        float mean=mv.x*inv, m2=mv.y*inv;
        float sd=sqrtf(fmaxf(m2-mean*mean,0.f));
        res[i]=sd*(ci[i]-cmv)*cr+mean;
    }
    float4 ro={res[0],res[1],res[2],res[3]};
    *(float4*)&out[oi]=ro;
}

// ---------------- launch ----------------
extern "C" void kernel_launch(void* const* d_in, const int* in_sizes, int n_in,
                              void* d_out, int out_size){
    const float* content     = (const float*)d_in[0];
    const float* style       = (const float*)d_in[1];
    const float* content_key = (const float*)d_in[2];
    const float* style_key   = (const float*)d_in[3];
    const int*   cmask       = (const int*)d_in[4];
    const int*   smask       = (const int*)d_in[5];
    const float* Wf=(const float*)d_in[6];  const float* bf=(const float*)d_in[7];
    const float* Wg=(const float*)d_in[8];  const float* bg=(const float*)d_in[9];
    const float* Wh=(const float*)d_in[10]; const float* bh=(const float*)d_in[11];
    float* out=(float*)d_out;

    __half *qh,*kh,*cth,*ctl,*sth,*stl,*wf16,*wg16;
    cudaGetSymbolAddress((void**)&qh,  g_Qh);
    cudaGetSymbolAddress((void**)&kh,  g_Kh);
    cudaGetSymbolAddress((void**)&cth, g_CTh); cudaGetSymbolAddress((void**)&ctl, g_CTl);
    cudaGetSymbolAddress((void**)&sth, g_STh); cudaGetSymbolAddress((void**)&stl, g_STl);
    cudaGetSymbolAddress((void**)&wf16, g_Wf16); cudaGetSymbolAddress((void**)&wg16, g_Wg16);
    cudaFuncSetAttribute(proj_mma_kernel,  cudaFuncAttributeMaxDynamicSharedMemorySize, PJ_SMEM);
    cudaFuncSetAttribute(projv_mma_kernel, cudaFuncAttributeMaxDynamicSharedMemorySize, VJ_SMEM);
    cudaFuncSetAttribute(sgemm_kernel, cudaFuncAttributeMaxDynamicSharedMemorySize, SG_SMEM);
    cudaFuncSetAttribute(pv_kernel,    cudaFuncAttributeMaxDynamicSharedMemorySize, PV_SMEM);

    megaprep_kernel<<<MP_BLOCKS, 256>>>(content, content_key, style_key, style, smask,
                                        Wf, Wg, Wh);
    proj_mma_kernel<<<dim3(7, 16, B_), 256, PJ_SMEM>>>(cth, ctl, wf16, bf, qh);
    proj_mma_kernel<<<dim3(7, 16, B_), 256, PJ_SMEM>>>(sth, stl, wg16, bg, kh);
    sgemm_kernel<<<dim3(16, 32, B_), 256, SG_SMEM>>>();
    projv_mma_kernel<<<dim3(4, 16, B_), 256, VJ_SMEM>>>(bh);
    softmax_kernel<<<dim3(N_, B_), 256>>>(cmask);
    pv_kernel<<<dim3(2, 32, B_), 256, PV_SMEM>>>();
    final_kernel<<<dim3(4, C_, B_), 256>>>(content, out);
}

// round 12
// speedup vs baseline: 1.6997x; 1.0573x over previous
#include <cuda_runtime.h>
#include <cuda_fp16.h>
#include <cstdint>

#define B_   4
#define C_   256
#define CK_  448
#define N_   4096
#define NEGV (-1e15f)

// ---------------- device scratch ----------------
__device__ __half g_Qh[(size_t)B_*N_*CK_];
__device__ __half g_Kh[(size_t)B_*N_*CK_];
__device__ __half g_VTh[(size_t)B_*C_*N_];     // [b][c][n]  (v only; v^2 derived in-reg)
__device__ float  g_S[(size_t)B_*N_*N_];       // [b][q][k] fp32 scores
__device__ __half g_P[(size_t)B_*N_*N_];       // [b][q][k]
__device__ float  g_l[B_*N_];
__device__ float  g_O[(size_t)B_*N_*2*C_];     // [b][q][2c interleaved: mean,m2]
__device__ float  g_cmean[B_*C_], g_crstd[B_*C_];
__device__ float  g_addm[B_*N_];               // additive key mask
// transposed fp16 hi/lo inputs: [b][n][c]
__device__ __half g_CTh[(size_t)B_*N_*CK_], g_CTl[(size_t)B_*N_*CK_];
__device__ __half g_STh[(size_t)B_*N_*CK_], g_STl[(size_t)B_*N_*CK_];
__device__ __half g_SVh[(size_t)B_*N_*C_],  g_SVl[(size_t)B_*N_*C_];
__device__ __half g_Wf16[CK_*CK_], g_Wg16[CK_*CK_];
__device__ __half g_Whh[C_*C_],    g_Whl[C_*C_];

// ---------------- mma.sync / ldmatrix / cp.async ----------------
__device__ __forceinline__ uint32_t smem_to_u32(const void*p){
    uint32_t a;asm("{ .reg .u64 t; cvta.to.shared.u64 t, %1; cvt.u32.u64 %0, t; }":"=r"(a):"l"(p));return a;}
__device__ __forceinline__ void mma16816(float* c, const uint32_t* a, const uint32_t* b){
    asm volatile("mma.sync.aligned.m16n8k16.row.col.f32.f16.f16.f32 "
        "{%0,%1,%2,%3}, {%4,%5,%6,%7}, {%8,%9}, {%0,%1,%2,%3};"
        : "+f"(c[0]),"+f"(c[1]),"+f"(c[2]),"+f"(c[3])
        : "r"(a[0]),"r"(a[1]),"r"(a[2]),"r"(a[3]), "r"(b[0]),"r"(b[1]));
}
__device__ __forceinline__ void ldm4(uint32_t* r, uint32_t addr){
    asm volatile("ldmatrix.sync.aligned.m8n8.x4.shared.b16 {%0,%1,%2,%3}, [%4];"
        :"=r"(r[0]),"=r"(r[1]),"=r"(r[2]),"=r"(r[3]):"r"(addr));
}
__device__ __forceinline__ void cp16(uint32_t dst, const void* src){
    asm volatile("cp.async.cg.shared.global [%0], [%1], 16;" :: "r"(dst), "l"(src));
}
#define CP_COMMIT() asm volatile("cp.async.commit_group;" ::: "memory")
#define CP_WAIT2()  asm volatile("cp.async.wait_group 2;" ::: "memory")
#define CP_WAIT1()  asm volatile("cp.async.wait_group 1;" ::: "memory")
#define CP_WAIT0()  asm volatile("cp.async.wait_group 0;" ::: "memory")

// ---------------- fast exp on fma pipe ----------------
__device__ __forceinline__ float fast_exp(float x){
    float t = fmaxf(x * 1.4426950408889634f, -126.0f);
    float fi = t + 12582912.0f;
    int i = __float_as_int(fi) - 0x4B400000;
    float f = t - (fi - 12582912.0f);
    float p = 1.5424236e-4f;
    p = fmaf(p,f,1.3333558e-3f); p = fmaf(p,f,9.6181291e-3f);
    p = fmaf(p,f,5.5504109e-2f); p = fmaf(p,f,2.4022651e-1f);
    p = fmaf(p,f,6.9314718e-1f); p = fmaf(p,f,1.0f);
    return __int_as_float(__float_as_int(p) + (i<<23));
}
__device__ __forceinline__ void hsplit(float y, __half& h, __half& l){
    h = __float2half_rn(y); l = __float2half_rn(y - __half2float(h));
}

// ---------------- megaprep: stats + transposes + weight converts + mask ----------------
#define MPB_STATS 0
#define MPB_TCK1  1024
#define MPB_TCK2  (MPB_TCK1+7168)
#define MPB_TC    (MPB_TCK2+7168)
#define MPB_WF    (MPB_TC+4096)
#define MPB_WG    (MPB_WF+196)
#define MPB_WHS   (MPB_WG+196)
#define MPB_MSK   (MPB_WHS+64)
#define MP_BLOCKS (MPB_MSK+64)

__device__ void dev_transpose(const float* __restrict__ X, __half* __restrict__ Th,
                              __half* __restrict__ Tl, int CIN, int t, float (*ts)[33]){
    int cper = CIN/32;
    int nb = t & 127, cb = (t>>7) % cper, b = t/(128*cper);
    int n0 = nb*32, c0 = cb*32;
    int tid=threadIdx.x, nl=tid&31, cw=tid>>5;
    #pragma unroll
    for(int i=0;i<4;i++){
        int c=cw+i*8;
        ts[c][nl]=X[((size_t)b*CIN + c0+c)*N_ + n0+nl];
    }
    __syncthreads();
    int n=tid>>3, c4=(tid&7)*4;
    __align__(8) __half hh[4], hl[4];
    #pragma unroll
    for(int j=0;j<4;j++) hsplit(ts[c4+j][n], hh[j], hl[j]);
    size_t o=((size_t)b*N_ + n0+n)*CIN + c0+c4;
    *(uint2*)&Th[o]=*(uint2*)hh;
    *(uint2*)&Tl[o]=*(uint2*)hl;
}

__global__ __launch_bounds__(256) void megaprep_kernel(const float* __restrict__ content,
        const float* __restrict__ content_key, const float* __restrict__ style_key,
        const float* __restrict__ style, const int* __restrict__ smask,
        const float* __restrict__ Wf, const float* __restrict__ Wg,
        const float* __restrict__ Wh){
    __shared__ float ts[32][33];
    __shared__ float r1[8], r2[8];
    int bid=blockIdx.x, tid=threadIdx.x;
    if(bid < MPB_TCK1){
        int bc=bid;
        const float4* x = (const float4*)(content + (size_t)bc*N_);
        float s=0.f,q=0.f;
        for(int i=tid;i<N_/4;i+=256){float4 v=x[i];s+=v.x+v.y+v.z+v.w;q+=v.x*v.x+v.y*v.y+v.z*v.z+v.w*v.w;}
        #pragma unroll
        for(int o=16;o;o>>=1){s+=__shfl_xor_sync(~0u,s,o);q+=__shfl_xor_sync(~0u,q,o);}
        int w=tid>>5,l=tid&31;
        if(l==0){r1[w]=s;r2[w]=q;}
        __syncthreads();
        if(tid==0){
            float S=0,Q=0;
            #pragma unroll
            for(int i=0;i<8;i++){S+=r1[i];Q+=r2[i];}
            float mean=S/(float)N_;
            float var=(Q-(float)N_*mean*mean)/(float)(N_-1);
            g_cmean[bc]=mean; g_crstd[bc]=rsqrtf(var+1e-5f);
        }
    } else if(bid < MPB_TCK2){
        dev_transpose(content_key, g_CTh, g_CTl, CK_, bid-MPB_TCK1, ts);
    } else if(bid < MPB_TC){
        dev_transpose(style_key, g_STh, g_STl, CK_, bid-MPB_TCK2, ts);
    } else if(bid < MPB_WF){
        dev_transpose(style, g_SVh, g_SVl, C_, bid-MPB_TC, ts);
    } else if(bid < MPB_WG){
        int i=(bid-MPB_WF)*256+tid;
        float4 v=((const float4*)Wf)[i];
        __align__(8) __half h[4];
        h[0]=__float2half_rn(v.x); h[1]=__float2half_rn(v.y);
        h[2]=__float2half_rn(v.z); h[3]=__float2half_rn(v.w);
        ((uint2*)g_Wf16)[i]=*(uint2*)h;
    } else if(bid < MPB_WHS){
        int i=(bid-MPB_WG)*256+tid;
        float4 v=((const float4*)Wg)[i];
        __align__(8) __half h[4];
        h[0]=__float2half_rn(v.x); h[1]=__float2half_rn(v.y);
        h[2]=__float2half_rn(v.z); h[3]=__float2half_rn(v.w);
        ((uint2*)g_Wg16)[i]=*(uint2*)h;
    } else if(bid < MPB_MSK){
        int i=(bid-MPB_WHS)*256+tid;
        float4 v=((const float4*)Wh)[i];
        __align__(8) __half hh[4], hl[4];
        float vv[4]={v.x,v.y,v.z,v.w};
        #pragma unroll
        for(int j=0;j<4;j++) hsplit(vv[j],hh[j],hl[j]);
        ((uint2*)g_Whh)[i]=*(uint2*)hh;
        ((uint2*)g_Whl)[i]=*(uint2*)hl;
    } else {
        int i=(bid-MPB_MSK)*256+tid;
        g_addm[i] = smask[i] ? 0.f : NEGV;
    }
}

// ---------------- proj Q/K via HMMA (2-term, validated) ----------------
#define PJ_AH 0
#define PJ_AL 36864
#define PJ_B  73728
#define PJ_STAGE 82944
#define PJ_SMEM (2*PJ_STAGE)
__global__ __launch_bounds__(256) void proj_mma_kernel(const __half* __restrict__ Xth,
                                                       const __half* __restrict__ Xtl,
                                                       const __half* __restrict__ W16,
                                                       const float* __restrict__ bias,
                                                       __half* __restrict__ Y){
    extern __shared__ char sm[];
    uint32_t sb = smem_to_u32(sm);
    int tid=threadIdx.x, lane=tid&31, wid=tid>>5;
    int g=lane>>2, tig=lane&3;
    int wq=wid&3, wk=wid>>2;
    int lrow=lane&15, lcol=lane>>4;
    int b=blockIdx.z, n0=blockIdx.y*256, o0=blockIdx.x*64;
    const __half* Ah = Xth + ((size_t)(b*N_)+n0)*CK_;
    const __half* Al = Xtl + ((size_t)(b*N_)+n0)*CK_;

    auto issue=[&](int ch, int st){
        uint32_t base = sb + st*PJ_STAGE;
        int ck0=ch*64;
        for(int i=tid;i<2048;i+=256){
            int r=i>>3, s=i&7;
            size_t gi=(size_t)r*CK_ + ck0 + s*8;
            cp16(base+PJ_AH + r*144 + s*16, Ah + gi);
            cp16(base+PJ_AL + r*144 + s*16, Al + gi);
        }
        for(int i=tid;i<512;i+=256){
            int r=i>>3, s=i&7;
            cp16(base+PJ_B + r*144 + s*16, W16 + (size_t)(o0+r)*CK_ + ck0 + s*8);
        }
    };

    float acc[4][4][4];
    #pragma unroll
    for(int mi=0;mi<4;mi++)
        #pragma unroll
        for(int ni=0;ni<4;ni++)
            #pragma unroll
            for(int e=0;e<4;e++) acc[mi][ni][e]=0.f;

    issue(0,0); CP_COMMIT();
    for(int ch=0; ch<7; ch++){
        if(ch+1<7){ issue(ch+1,(ch+1)&1); CP_COMMIT(); CP_WAIT1(); } else { CP_WAIT0(); }
        __syncthreads();
        uint32_t stg = sb + (ch&1)*PJ_STAGE;
        #pragma unroll
        for(int ks=0;ks<4;ks++){
            int kbo = (ks*16 + lcol*8)*2;
            uint32_t bh[4][2];
            #pragma unroll
            for(int nb=0;nb<2;nb++){
                uint32_t r4[4];
                ldm4(r4, stg+PJ_B + (wk*32+nb*16+lrow)*144 + kbo);
                bh[2*nb][0]=r4[0]; bh[2*nb+1][0]=r4[1]; bh[2*nb][1]=r4[2]; bh[2*nb+1][1]=r4[3];
            }
            #pragma unroll
            for(int mi=0;mi<4;mi++){
                uint32_t ah[4], al[4];
                uint32_t off = (wq*64+mi*16+lrow)*144 + kbo;
                ldm4(ah, stg+PJ_AH + off);
                ldm4(al, stg+PJ_AL + off);
                #pragma unroll
                for(int ni=0;ni<4;ni++){
                    mma16816(acc[mi][ni], ah, bh[ni]);
                    mma16816(acc[mi][ni], al, bh[ni]);
                }
            }
        }
        __syncthreads();
    }
    #pragma unroll
    for(int mi=0;mi<4;mi++){
        int qr=wq*64+mi*16+g;
        #pragma unroll
        for(int ni=0;ni<4;ni++){
            int oc=wk*32+ni*8+tig*2;
            float2 bia=*(const float2*)&bias[o0+oc];
            __half2 h0=__floats2half2_rn(acc[mi][ni][0]+bia.x, acc[mi][ni][1]+bia.y);
            __half2 h1=__floats2half2_rn(acc[mi][ni][2]+bia.x, acc[mi][ni][3]+bia.y);
            *(__half2*)&Y[((size_t)(b*N_)+n0+qr)*CK_ + o0+oc]   = h0;
            *(__half2*)&Y[((size_t)(b*N_)+n0+qr+8)*CK_ + o0+oc] = h1;
        }
    }
}

// ---------------- projV via HMMA (3-term; v only, transposed out) ----------------
#define VJ_AH 0
#define VJ_AL 36864
#define VJ_BH 73728
#define VJ_BL 82944
#define VJ_STAGE 92160
#define VJ_SMEM (2*VJ_STAGE)
__global__ __launch_bounds__(256) void projv_mma_kernel(const float* __restrict__ bias){
    extern __shared__ char sm[];
    uint32_t sb = smem_to_u32(sm);
    int tid=threadIdx.x, lane=tid&31, wid=tid>>5;
    int g=lane>>2, tig=lane&3;
    int wq=wid&3, wk=wid>>2;
    int lrow=lane&15, lcol=lane>>4;
    int b=blockIdx.z, n0=blockIdx.y*256, o0=blockIdx.x*64;
    const __half* Ah = g_SVh + ((size_t)(b*N_)+n0)*C_;
    const __half* Al = g_SVl + ((size_t)(b*N_)+n0)*C_;

    auto issue=[&](int ch, int st){
        uint32_t base = sb + st*VJ_STAGE;
        int ck0=ch*64;
        for(int i=tid;i<2048;i+=256){
            int r=i>>3, s=i&7;
            size_t gi=(size_t)r*C_ + ck0 + s*8;
            cp16(base+VJ_AH + r*144 + s*16, Ah + gi);
            cp16(base+VJ_AL + r*144 + s*16, Al + gi);
        }
        for(int i=tid;i<512;i+=256){
            int r=i>>3, s=i&7;
            size_t gi=(size_t)(o0+r)*C_ + ck0 + s*8;
            cp16(base+VJ_BH + r*144 + s*16, g_Whh + gi);
            cp16(base+VJ_BL + r*144 + s*16, g_Whl + gi);
        }
    };

    float acc[4][4][4];
    #pragma unroll
    for(int mi=0;mi<4;mi++)
        #pragma unroll
        for(int ni=0;ni<4;ni++)
            #pragma unroll
            for(int e=0;e<4;e++) acc[mi][ni][e]=0.f;

    issue(0,0); CP_COMMIT();
    for(int ch=0; ch<4; ch++){
        if(ch+1<4){ issue(ch+1,(ch+1)&1); CP_COMMIT(); CP_WAIT1(); } else { CP_WAIT0(); }
        __syncthreads();
        uint32_t stg = sb + (ch&1)*VJ_STAGE;
        #pragma unroll
        for(int ks=0;ks<4;ks++){
            int kbo = (ks*16 + lcol*8)*2;
            uint32_t bh[4][2], bl[4][2];
            #pragma unroll
            for(int nb=0;nb<2;nb++){
                uint32_t r4[4];
                uint32_t off = (wk*32+nb*16+lrow)*144 + kbo;
                ldm4(r4, stg+VJ_BH + off);
                bh[2*nb][0]=r4[0]; bh[2*nb+1][0]=r4[1]; bh[2*nb][1]=r4[2]; bh[2*nb+1][1]=r4[3];
                ldm4(r4, stg+VJ_BL + off);
                bl[2*nb][0]=r4[0]; bl[2*nb+1][0]=r4[1]; bl[2*nb][1]=r4[2]; bl[2*nb+1][1]=r4[3];
            }
            #pragma unroll
            for(int mi=0;mi<4;mi++){
                uint32_t ah[4], al[4];
                uint32_t off = (wq*64+mi*16+lrow)*144 + kbo;
                ldm4(ah, stg+VJ_AH + off);
                ldm4(al, stg+VJ_AL + off);
                #pragma unroll
                for(int ni=0;ni<4;ni++){
                    mma16816(acc[mi][ni], ah, bh[ni]);
                    mma16816(acc[mi][ni], ah, bl[ni]);
                    mma16816(acc[mi][ni], al, bh[ni]);
                }
            }
        }
        __syncthreads();
    }
    // epilogue: y -> smem [64 o-rows][264 n] -> coalesced VT store (v only)
    __half* ep = (__half*)sm;
    #pragma unroll
    for(int mi=0;mi<4;mi++){
        int qr=wq*64+mi*16+g;
        #pragma unroll
        for(int ni=0;ni<4;ni++){
            int oc=wk*32+ni*8+tig*2;
            float2 bia=*(const float2*)&bias[o0+oc];
            ep[(oc+0)*264+qr]   = __float2half_rn(acc[mi][ni][0]+bia.x);
            ep[(oc+1)*264+qr]   = __float2half_rn(acc[mi][ni][1]+bia.y);
            ep[(oc+0)*264+qr+8] = __float2half_rn(acc[mi][ni][2]+bia.x);
            ep[(oc+1)*264+qr+8] = __float2half_rn(acc[mi][ni][3]+bia.y);
        }
    }
    __syncthreads();
    __half* VTo = g_VTh + ((size_t)b*C_ + o0)*N_ + n0;
    for(int e=tid;e<2048;e+=256){
        int r=e>>5, c=(e&31)*8;
        *(uint4*)&VTo[(size_t)r*N_ + c] = *(uint4*)&ep[r*264 + c];
    }
}

// ---------------- sgemm: S = Q K^T  (validated, untouched) ----------------
#define SG_Q  0
#define SG_KH 18432
#define SG_STAGE 55296
#define SG_SMEM (3*SG_STAGE)
__global__ __launch_bounds__(256) void sgemm_kernel(){
    extern __shared__ char sm[];
    uint32_t sb = smem_to_u32(sm);
    int tid=threadIdx.x, lane=tid&31, wid=tid>>5;
    int g=lane>>2, tig=lane&3;
    int wq=wid&1, wk=wid>>1;
    int lrow=lane&15, lcol=lane>>4;
    int b=blockIdx.z, q0=blockIdx.y*128, k0=blockIdx.x*256;
    const __half* Qg=g_Qh+((size_t)b*N_+q0)*CK_;
    const __half* Khg=g_Kh+((size_t)b*N_+k0)*CK_;

    auto issue=[&](int ch, int st){
        uint32_t base = sb + st*SG_STAGE;
        int ck0=ch*64;
        for(int i=tid;i<1024;i+=256){
            int r=i>>3, s=i&7;
            cp16(base+SG_Q + r*144 + s*16, Qg + (size_t)r*CK_ + ck0 + s*8);
        }
        for(int i=tid;i<2048;i+=256){
            int r=i>>3, s=i&7;
            cp16(base+SG_KH + r*144 + s*16, Khg + (size_t)r*CK_ + ck0 + s*8);
        }
    };

    float acc[4][8][4];
    #pragma unroll
    for(int mi=0;mi<4;mi++)
        #pragma unroll
        for(int ni=0;ni<8;ni++)
            #pragma unroll
            for(int e=0;e<4;e++) acc[mi][ni][e]=0.f;

    issue(0,0); CP_COMMIT();
    issue(1,1); CP_COMMIT();
    int st=2;
    for(int ch=0; ch<7; ch++){
        if(ch+2<7){ issue(ch+2,st); CP_COMMIT(); st=(st+1==3)?0:st+1; CP_WAIT2(); }
        else if(ch+1<7){ CP_WAIT1(); }
        else { CP_WAIT0(); }
        __syncthreads();
        uint32_t stg = sb + (ch%3)*SG_STAGE;
        #pragma unroll
        for(int ks=0;ks<4;ks++){
            int kbo = (ks*16 + lcol*8)*2;
            uint32_t bh[8][2];
            #pragma unroll
            for(int nb=0;nb<4;nb++){
                uint32_t r4[4];
                ldm4(r4, stg+SG_KH + (wk*64+nb*16+lrow)*144 + kbo);
                bh[2*nb][0]=r4[0]; bh[2*nb+1][0]=r4[1]; bh[2*nb][1]=r4[2]; bh[2*nb+1][1]=r4[3];
            }
            #pragma unroll
            for(int mi=0;mi<4;mi++){
                uint32_t a[4];
                ldm4(a, stg+SG_Q + (wq*64+mi*16+lrow)*144 + kbo);
                #pragma unroll
                for(int ni=0;ni<8;ni++) mma16816(acc[mi][ni], a, bh[ni]);
            }
        }
        __syncthreads();
    }
    float* So = g_S + ((size_t)b*N_+q0)*N_ + k0;
    #pragma unroll
    for(int mi=0;mi<4;mi++){
        int qr=wq*64+mi*16+g;
        #pragma unroll
        for(int ni=0;ni<8;ni++){
            int kc=wk*64+ni*8+tig*2;
            float2 v0={acc[mi][ni][0],acc[mi][ni][1]};
            float2 v1={acc[mi][ni][2],acc[mi][ni][3]};
            *(float2*)&So[(size_t)qr*N_+kc]     = v0;
            *(float2*)&So[(size_t)(qr+8)*N_+kc] = v1;
        }
    }
}

// ---------------- softmax (additive mask, fp32 S, fp16 P) ----------------
__global__ __launch_bounds__(256) void softmax_kernel(const int* __restrict__ cmask){
    int b=blockIdx.y, q=blockIdx.x, tid=threadIdx.x;
    const float4* Srow=(const float4*)(g_S+((size_t)b*N_+q)*N_);
    const float4* Am=(const float4*)(g_addm + b*N_);
    float cmf = (cmask[b*N_+q]!=0) ? 1.f : 0.f;
    float s[16], mx=-3.4e38f;
    #pragma unroll
    for(int i=0;i<4;i++){
        int k4=tid+i*256;
        float4 v=Srow[k4];
        float4 a=Am[k4];
        v.x=fmaf(cmf,a.x,v.x); v.y=fmaf(cmf,a.y,v.y);
        v.z=fmaf(cmf,a.z,v.z); v.w=fmaf(cmf,a.w,v.w);
        s[4*i]=v.x;s[4*i+1]=v.y;s[4*i+2]=v.z;s[4*i+3]=v.w;
        mx=fmaxf(mx,fmaxf(fmaxf(v.x,v.y),fmaxf(v.z,v.w)));
    }
    #pragma unroll
    for(int o=16;o;o>>=1) mx=fmaxf(mx,__shfl_xor_sync(~0u,mx,o));
    __shared__ float red[8];
    int w=tid>>5,l=tid&31;
    if(l==0) red[w]=mx;
    __syncthreads();
    float M=red[0];
    #pragma unroll
    for(int i=1;i<8;i++) M=fmaxf(M,red[i]);
    __syncthreads();
    float sum=0.f;
    uint2* Prow=(uint2*)(g_P+((size_t)b*N_+q)*N_);
    #pragma unroll
    for(int i=0;i<4;i++){
        __align__(8) __half h[4];
        #pragma unroll
        for(int j=0;j<4;j++){
            float p=fast_exp(s[4*i+j]-M);
            h[j]=__float2half_rn(p);
            sum+=__half2float(h[j]);
        }
        Prow[tid+i*256]=*(uint2*)h;
    }
    #pragma unroll
    for(int o=16;o;o>>=1) sum+=__shfl_xor_sync(~0u,sum,o);
    if(l==0) red[w]=sum;
    __syncthreads();
    if(tid==0){
        float t=0.f;
        #pragma unroll
        for(int i=0;i<8;i++) t+=red[i];
        g_l[b*N_+q]=t;
    }
}

// ---------------- pv: mean/m2 = P * [V;V^2], V^2 derived in-register ----------------
// CTA 128q x 128c, 8 warps (64q x 32c), dual accumulators.
#define PV_P 0
#define PV_V 18432
#define PV_STAGE 36864
#define PV_SMEM (3*PV_STAGE)
__global__ __launch_bounds__(256) void pv_kernel(){
    extern __shared__ char sm[];
    uint32_t sb = smem_to_u32(sm);
    int tid=threadIdx.x, lane=tid&31, wid=tid>>5;
    int g=lane>>2, tig=lane&3;
    int wq=wid&1, wk=wid>>1;
    int lrow=lane&15, lcol=lane>>4;
    int b=blockIdx.z, q0=blockIdx.y*128, c0=blockIdx.x*128;
    const __half* Pg = g_P  + ((size_t)b*N_+q0)*N_;
    const __half* Vg = g_VTh+ ((size_t)b*C_+c0)*N_;

    auto issue=[&](int ch, int st){
        uint32_t base = sb + st*PV_STAGE;
        int kk0=ch*64;
        for(int i=tid;i<1024;i+=256){
            int r=i>>3, s=i&7;
            cp16(base+PV_P + r*144 + s*16, Pg + (size_t)r*N_ + kk0 + s*8);
            cp16(base+PV_V + r*144 + s*16, Vg + (size_t)r*N_ + kk0 + s*8);
        }
    };

    float accm[4][4][4], accq[4][4][4];
    #pragma unroll
    for(int mi=0;mi<4;mi++)
        #pragma unroll
        for(int ni=0;ni<4;ni++)
            #pragma unroll
            for(int e=0;e<4;e++){ accm[mi][ni][e]=0.f; accq[mi][ni][e]=0.f; }

    issue(0,0); CP_COMMIT();
    issue(1,1); CP_COMMIT();
    int st=2;
    for(int ch=0; ch<64; ch++){
        if(ch+2<64){ issue(ch+2,st); CP_COMMIT(); st=(st+1==3)?0:st+1; CP_WAIT2(); }
        else if(ch+1<64){ CP_WAIT1(); }
        else { CP_WAIT0(); }
        __syncthreads();
        uint32_t stg = sb + (ch%3)*PV_STAGE;
        #pragma unroll
        for(int ks=0;ks<4;ks++){
            int kbo = (ks*16 + lcol*8)*2;
            uint32_t bh[4][2], bq[4][2];
            #pragma unroll
            for(int nb=0;nb<2;nb++){
                uint32_t r4[4];
                ldm4(r4, stg+PV_V + (wk*32+nb*16+lrow)*144 + kbo);
                bh[2*nb][0]=r4[0]; bh[2*nb+1][0]=r4[1]; bh[2*nb][1]=r4[2]; bh[2*nb+1][1]=r4[3];
            }
            #pragma unroll
            for(int ni=0;ni<4;ni++){
                #pragma unroll
                for(int r=0;r<2;r++){
                    __half2 hv = *(__half2*)&bh[ni][r];
                    __half2 sq = __hmul2(hv, hv);
                    bq[ni][r] = *(uint32_t*)&sq;
                }
            }
            #pragma unroll
            for(int mi=0;mi<4;mi++){
                uint32_t a[4];
                ldm4(a, stg+PV_P + (wq*64+mi*16+lrow)*144 + kbo);
                #pragma unroll
                for(int ni=0;ni<4;ni++){
                    mma16816(accm[mi][ni], a, bh[ni]);
                    mma16816(accq[mi][ni], a, bq[ni]);
                }
            }
        }
        __syncthreads();
    }
    // epilogue: interleave mean/m2 -> g_O[q][2c], float4 per (mi,ni,row)
    float* Ob = g_O + ((size_t)b*N_+q0)*(2*C_) + 2*c0;
    #pragma unroll
    for(int mi=0;mi<4;mi++){
        int qr=wq*64+mi*16+g;
        #pragma unroll
        for(int ni=0;ni<4;ni++){
            int cc=wk*32+ni*8+tig*2;
            float4 v0={accm[mi][ni][0],accq[mi][ni][0],accm[mi][ni][1],accq[mi][ni][1]};
            float4 v1={accm[mi][ni][2],accq[mi][ni][2],accm[mi][ni][3],accq[mi][ni][3]};
            *(float4*)&Ob[(size_t)qr*(2*C_)+2*cc]     = v0;
            *(float4*)&Ob[(size_t)(qr+8)*(2*C_)+2*cc] = v1;
        }
    }
}

// ---------------- finalize ----------------
__global__ __launch_bounds__(256) void final_kernel(const float* __restrict__ content,
                                                    float* __restrict__ out){
    int b=blockIdx.z, c=blockIdx.y;
    int n=(blockIdx.x*256+threadIdx.x)*4;
    const float* Ob=g_O+(size_t)b*N_*(2*C_);
    float4 l4=*(const float4*)&g_l[b*N_+n];
    float lv[4]={l4.x,l4.y,l4.z,l4.w};
    float cmv=g_cmean[b*C_+c], cr=g_crstd[b*C_+c];
    size_t oi=((size_t)(b*C_+c))*N_+n;
    float4 cx=*(const float4*)&content[oi];
    float ci[4]={cx.x,cx.y,cx.z,cx.w};
    float res[4];
    #pragma unroll
    for(int i=0;i<4;i++){
        float2 mv=*(const float2*)&Ob[(size_t)(n+i)*(2*C_)+2*c];
        float inv=1.0f/lv[i];
        float mean=mv.x*inv, m2=mv.y*inv;
        float sd=sqrtf(fmaxf(m2-mean*mean,0.f));
        res[i]=sd*(ci[i]-cmv)*cr+mean;
    }
    float4 ro={res[0],res[1],res[2],res[3]};
    *(float4*)&out[oi]=ro;
}

// ---------------- launch ----------------
extern "C" void kernel_launch(void* const* d_in, const int* in_sizes, int n_in,
                              void* d_out, int out_size){
    const float* content     = (const float*)d_in[0];
    const float* style       = (const float*)d_in[1];
    const float* content_key = (const float*)d_in[2];
    const float* style_key   = (const float*)d_in[3];
    const int*   cmask       = (const int*)d_in[4];
    const int*   smask       = (const int*)d_in[5];
    const float* Wf=(const float*)d_in[6];  const float* bf=(const float*)d_in[7];
    const float* Wg=(const float*)d_in[8];  const float* bg=(const float*)d_in[9];
    const float* Wh=(const float*)d_in[10]; const float* bh=(const float*)d_in[11];
    float* out=(float*)d_out;

    __half *qh,*kh,*cth,*ctl,*sth,*stl,*wf16,*wg16;
    cudaGetSymbolAddress((void**)&qh,  g_Qh);
    cudaGetSymbolAddress((void**)&kh,  g_Kh);
    cudaGetSymbolAddress((void**)&cth, g_CTh); cudaGetSymbolAddress((void**)&ctl, g_CTl);
    cudaGetSymbolAddress((void**)&sth, g_STh); cudaGetSymbolAddress((void**)&stl, g_STl);
    cudaGetSymbolAddress((void**)&wf16, g_Wf16); cudaGetSymbolAddress((void**)&wg16, g_Wg16);
    cudaFuncSetAttribute(proj_mma_kernel,  cudaFuncAttributeMaxDynamicSharedMemorySize, PJ_SMEM);
    cudaFuncSetAttribute(projv_mma_kernel, cudaFuncAttributeMaxDynamicSharedMemorySize, VJ_SMEM);
    cudaFuncSetAttribute(sgemm_kernel, cudaFuncAttributeMaxDynamicSharedMemorySize, SG_SMEM);
    cudaFuncSetAttribute(pv_kernel,    cudaFuncAttributeMaxDynamicSharedMemorySize, PV_SMEM);

    megaprep_kernel<<<MP_BLOCKS, 256>>>(content, content_key, style_key, style, smask,
                                        Wf, Wg, Wh);
    proj_mma_kernel<<<dim3(7, 16, B_), 256, PJ_SMEM>>>(cth, ctl, wf16, bf, qh);
    proj_mma_kernel<<<dim3(7, 16, B_), 256, PJ_SMEM>>>(sth, stl, wg16, bg, kh);
    sgemm_kernel<<<dim3(16, 32, B_), 256, SG_SMEM>>>();
    projv_mma_kernel<<<dim3(4, 16, B_), 256, VJ_SMEM>>>(bh);
    softmax_kernel<<<dim3(N_, B_), 256>>>(cmask);
    pv_kernel<<<dim3(2, 32, B_), 256, PV_SMEM>>>();
    final_kernel<<<dim3(4, C_, B_), 256>>>(content, out);
}

// round 13
// speedup vs baseline: 1.7035x; 1.0023x over previous
#include <cuda_runtime.h>
#include <cuda_fp16.h>
#include <cstdint>

#define B_   4
#define C_   256
#define CK_  448
#define N_   4096
#define NEGV (-1e15f)

// ---------------- device scratch ----------------
__device__ __half g_Qh[(size_t)B_*N_*CK_];
__device__ __half g_Kh[(size_t)B_*N_*CK_];
__device__ __half g_VTh[(size_t)B_*C_*N_];     // [b][c][n]  (v only; v^2 derived in-reg)
__device__ float  g_S[(size_t)B_*N_*N_];       // [b][q][k] fp32 scores
__device__ __half g_P[(size_t)B_*N_*N_];       // [b][q][k]
__device__ float  g_l[B_*N_];
__device__ float  g_O[(size_t)B_*N_*2*C_];     // [b][q][2c interleaved: mean,m2]
__device__ float  g_cmean[B_*C_], g_crstd[B_*C_];
__device__ float  g_addm[B_*N_];               // additive key mask
// transposed fp16 hi/lo inputs: [b][n][c]
__device__ __half g_CTh[(size_t)B_*N_*CK_], g_CTl[(size_t)B_*N_*CK_];
__device__ __half g_STh[(size_t)B_*N_*CK_], g_STl[(size_t)B_*N_*CK_];
__device__ __half g_SVh[(size_t)B_*N_*C_],  g_SVl[(size_t)B_*N_*C_];
__device__ __half g_Wf16[CK_*CK_], g_Wg16[CK_*CK_];
__device__ __half g_Whh[C_*C_],    g_Whl[C_*C_];

// ---------------- mma.sync / ldmatrix / cp.async ----------------
__device__ __forceinline__ uint32_t smem_to_u32(const void*p){
    uint32_t a;asm("{ .reg .u64 t; cvta.to.shared.u64 t, %1; cvt.u32.u64 %0, t; }":"=r"(a):"l"(p));return a;}
__device__ __forceinline__ void mma16816(float* c, const uint32_t* a, const uint32_t* b){
    asm volatile("mma.sync.aligned.m16n8k16.row.col.f32.f16.f16.f32 "
        "{%0,%1,%2,%3}, {%4,%5,%6,%7}, {%8,%9}, {%0,%1,%2,%3};"
        : "+f"(c[0]),"+f"(c[1]),"+f"(c[2]),"+f"(c[3])
        : "r"(a[0]),"r"(a[1]),"r"(a[2]),"r"(a[3]), "r"(b[0]),"r"(b[1]));
}
__device__ __forceinline__ void ldm4(uint32_t* r, uint32_t addr){
    asm volatile("ldmatrix.sync.aligned.m8n8.x4.shared.b16 {%0,%1,%2,%3}, [%4];"
        :"=r"(r[0]),"=r"(r[1]),"=r"(r[2]),"=r"(r[3]):"r"(addr));
}
__device__ __forceinline__ void cp16(uint32_t dst, const void* src){
    asm volatile("cp.async.cg.shared.global [%0], [%1], 16;" :: "r"(dst), "l"(src));
}
#define CP_COMMIT() asm volatile("cp.async.commit_group;" ::: "memory")
#define CP_WAIT2()  asm volatile("cp.async.wait_group 2;" ::: "memory")
#define CP_WAIT1()  asm volatile("cp.async.wait_group 1;" ::: "memory")
#define CP_WAIT0()  asm volatile("cp.async.wait_group 0;" ::: "memory")

// ---------------- fast exp on fma pipe ----------------
__device__ __forceinline__ float fast_exp(float x){
    float t = fmaxf(x * 1.4426950408889634f, -126.0f);
    float fi = t + 12582912.0f;
    int i = __float_as_int(fi) - 0x4B400000;
    float f = t - (fi - 12582912.0f);
    float p = 1.5424236e-4f;
    p = fmaf(p,f,1.3333558e-3f); p = fmaf(p,f,9.6181291e-3f);
    p = fmaf(p,f,5.5504109e-2f); p = fmaf(p,f,2.4022651e-1f);
    p = fmaf(p,f,6.9314718e-1f); p = fmaf(p,f,1.0f);
    return __int_as_float(__float_as_int(p) + (i<<23));
}
__device__ __forceinline__ void hsplit(float y, __half& h, __half& l){
    h = __float2half_rn(y); l = __float2half_rn(y - __half2float(h));
}

// ---------------- megaprep: stats + transposes + weight converts + mask ----------------
#define MPB_STATS 0
#define MPB_TCK1  1024
#define MPB_TCK2  (MPB_TCK1+7168)
#define MPB_TC    (MPB_TCK2+7168)
#define MPB_WF    (MPB_TC+4096)
#define MPB_WG    (MPB_WF+196)
#define MPB_WHS   (MPB_WG+196)
#define MPB_MSK   (MPB_WHS+64)
#define MP_BLOCKS (MPB_MSK+64)

__device__ void dev_transpose(const float* __restrict__ X, __half* __restrict__ Th,
                              __half* __restrict__ Tl, int CIN, int t, float (*ts)[33]){
    int cper = CIN/32;
    int nb = t & 127, cb = (t>>7) % cper, b = t/(128*cper);
    int n0 = nb*32, c0 = cb*32;
    int tid=threadIdx.x, nl=tid&31, cw=tid>>5;
    #pragma unroll
    for(int i=0;i<4;i++){
        int c=cw+i*8;
        ts[c][nl]=X[((size_t)b*CIN + c0+c)*N_ + n0+nl];
    }
    __syncthreads();
    int n=tid>>3, c4=(tid&7)*4;
    __align__(8) __half hh[4], hl[4];
    #pragma unroll
    for(int j=0;j<4;j++) hsplit(ts[c4+j][n], hh[j], hl[j]);
    size_t o=((size_t)b*N_ + n0+n)*CIN + c0+c4;
    *(uint2*)&Th[o]=*(uint2*)hh;
    *(uint2*)&Tl[o]=*(uint2*)hl;
}

__global__ __launch_bounds__(256) void megaprep_kernel(const float* __restrict__ content,
        const float* __restrict__ content_key, const float* __restrict__ style_key,
        const float* __restrict__ style, const int* __restrict__ smask,
        const float* __restrict__ Wf, const float* __restrict__ Wg,
        const float* __restrict__ Wh){
    __shared__ float ts[32][33];
    __shared__ float r1[8], r2[8];
    int bid=blockIdx.x, tid=threadIdx.x;
    if(bid < MPB_TCK1){
        int bc=bid;
        const float4* x = (const float4*)(content + (size_t)bc*N_);
        float s=0.f,q=0.f;
        for(int i=tid;i<N_/4;i+=256){float4 v=x[i];s+=v.x+v.y+v.z+v.w;q+=v.x*v.x+v.y*v.y+v.z*v.z+v.w*v.w;}
        #pragma unroll
        for(int o=16;o;o>>=1){s+=__shfl_xor_sync(~0u,s,o);q+=__shfl_xor_sync(~0u,q,o);}
        int w=tid>>5,l=tid&31;
        if(l==0){r1[w]=s;r2[w]=q;}
        __syncthreads();
        if(tid==0){
            float S=0,Q=0;
            #pragma unroll
            for(int i=0;i<8;i++){S+=r1[i];Q+=r2[i];}
            float mean=S/(float)N_;
            float var=(Q-(float)N_*mean*mean)/(float)(N_-1);
            g_cmean[bc]=mean; g_crstd[bc]=rsqrtf(var+1e-5f);
        }
    } else if(bid < MPB_TCK2){
        dev_transpose(content_key, g_CTh, g_CTl, CK_, bid-MPB_TCK1, ts);
    } else if(bid < MPB_TC){
        dev_transpose(style_key, g_STh, g_STl, CK_, bid-MPB_TCK2, ts);
    } else if(bid < MPB_WF){
        dev_transpose(style, g_SVh, g_SVl, C_, bid-MPB_TC, ts);
    } else if(bid < MPB_WG){
        int i=(bid-MPB_WF)*256+tid;
        float4 v=((const float4*)Wf)[i];
        __align__(8) __half h[4];
        h[0]=__float2half_rn(v.x); h[1]=__float2half_rn(v.y);
        h[2]=__float2half_rn(v.z); h[3]=__float2half_rn(v.w);
        ((uint2*)g_Wf16)[i]=*(uint2*)h;
    } else if(bid < MPB_WHS){
        int i=(bid-MPB_WG)*256+tid;
        float4 v=((const float4*)Wg)[i];
        __align__(8) __half h[4];
        h[0]=__float2half_rn(v.x); h[1]=__float2half_rn(v.y);
        h[2]=__float2half_rn(v.z); h[3]=__float2half_rn(v.w);
        ((uint2*)g_Wg16)[i]=*(uint2*)h;
    } else if(bid < MPB_MSK){
        int i=(bid-MPB_WHS)*256+tid;
        float4 v=((const float4*)Wh)[i];
        __align__(8) __half hh[4], hl[4];
        float vv[4]={v.x,v.y,v.z,v.w};
        #pragma unroll
        for(int j=0;j<4;j++) hsplit(vv[j],hh[j],hl[j]);
        ((uint2*)g_Whh)[i]=*(uint2*)hh;
        ((uint2*)g_Whl)[i]=*(uint2*)hl;
    } else {
        int i=(bid-MPB_MSK)*256+tid;
        g_addm[i] = smask[i] ? 0.f : NEGV;
    }
}

// ---------------- proj Q/K via HMMA (2-term, validated) ----------------
#define PJ_AH 0
#define PJ_AL 36864
#define PJ_B  73728
#define PJ_STAGE 82944
#define PJ_SMEM (2*PJ_STAGE)
__global__ __launch_bounds__(256) void proj_mma_kernel(const __half* __restrict__ Xth,
                                                       const __half* __restrict__ Xtl,
                                                       const __half* __restrict__ W16,
                                                       const float* __restrict__ bias,
                                                       __half* __restrict__ Y){
    extern __shared__ char sm[];
    uint32_t sb = smem_to_u32(sm);
    int tid=threadIdx.x, lane=tid&31, wid=tid>>5;
    int g=lane>>2, tig=lane&3;
    int wq=wid&3, wk=wid>>2;
    int lrow=lane&15, lcol=lane>>4;
    int b=blockIdx.z, n0=blockIdx.y*256, o0=blockIdx.x*64;
    const __half* Ah = Xth + ((size_t)(b*N_)+n0)*CK_;
    const __half* Al = Xtl + ((size_t)(b*N_)+n0)*CK_;

    auto issue=[&](int ch, int st){
        uint32_t base = sb + st*PJ_STAGE;
        int ck0=ch*64;
        for(int i=tid;i<2048;i+=256){
            int r=i>>3, s=i&7;
            size_t gi=(size_t)r*CK_ + ck0 + s*8;
            cp16(base+PJ_AH + r*144 + s*16, Ah + gi);
            cp16(base+PJ_AL + r*144 + s*16, Al + gi);
        }
        for(int i=tid;i<512;i+=256){
            int r=i>>3, s=i&7;
            cp16(base+PJ_B + r*144 + s*16, W16 + (size_t)(o0+r)*CK_ + ck0 + s*8);
        }
    };

    float acc[4][4][4];
    #pragma unroll
    for(int mi=0;mi<4;mi++)
        #pragma unroll
        for(int ni=0;ni<4;ni++)
            #pragma unroll
            for(int e=0;e<4;e++) acc[mi][ni][e]=0.f;

    issue(0,0); CP_COMMIT();
    for(int ch=0; ch<7; ch++){
        if(ch+1<7){ issue(ch+1,(ch+1)&1); CP_COMMIT(); CP_WAIT1(); } else { CP_WAIT0(); }
        __syncthreads();
        uint32_t stg = sb + (ch&1)*PJ_STAGE;
        #pragma unroll
        for(int ks=0;ks<4;ks++){
            int kbo = (ks*16 + lcol*8)*2;
            uint32_t bh[4][2];
            #pragma unroll
            for(int nb=0;nb<2;nb++){
                uint32_t r4[4];
                ldm4(r4, stg+PJ_B + (wk*32+nb*16+lrow)*144 + kbo);
                bh[2*nb][0]=r4[0]; bh[2*nb+1][0]=r4[1]; bh[2*nb][1]=r4[2]; bh[2*nb+1][1]=r4[3];
            }
            #pragma unroll
            for(int mi=0;mi<4;mi++){
                uint32_t ah[4], al[4];
                uint32_t off = (wq*64+mi*16+lrow)*144 + kbo;
                ldm4(ah, stg+PJ_AH + off);
                ldm4(al, stg+PJ_AL + off);
                #pragma unroll
                for(int ni=0;ni<4;ni++){
                    mma16816(acc[mi][ni], ah, bh[ni]);
                    mma16816(acc[mi][ni], al, bh[ni]);
                }
            }
        }
        __syncthreads();
    }
    #pragma unroll
    for(int mi=0;mi<4;mi++){
        int qr=wq*64+mi*16+g;
        #pragma unroll
        for(int ni=0;ni<4;ni++){
            int oc=wk*32+ni*8+tig*2;
            float2 bia=*(const float2*)&bias[o0+oc];
            __half2 h0=__floats2half2_rn(acc[mi][ni][0]+bia.x, acc[mi][ni][1]+bia.y);
            __half2 h1=__floats2half2_rn(acc[mi][ni][2]+bia.x, acc[mi][ni][3]+bia.y);
            *(__half2*)&Y[((size_t)(b*N_)+n0+qr)*CK_ + o0+oc]   = h0;
            *(__half2*)&Y[((size_t)(b*N_)+n0+qr+8)*CK_ + o0+oc] = h1;
        }
    }
}

// ---------------- projV via HMMA (3-term; v only, transposed out) ----------------
#define VJ_AH 0
#define VJ_AL 36864
#define VJ_BH 73728
#define VJ_BL 82944
#define VJ_STAGE 92160
#define VJ_SMEM (2*VJ_STAGE)
__global__ __launch_bounds__(256) void projv_mma_kernel(const float* __restrict__ bias){
    extern __shared__ char sm[];
    uint32_t sb = smem_to_u32(sm);
    int tid=threadIdx.x, lane=tid&31, wid=tid>>5;
    int g=lane>>2, tig=lane&3;
    int wq=wid&3, wk=wid>>2;
    int lrow=lane&15, lcol=lane>>4;
    int b=blockIdx.z, n0=blockIdx.y*256, o0=blockIdx.x*64;
    const __half* Ah = g_SVh + ((size_t)(b*N_)+n0)*C_;
    const __half* Al = g_SVl + ((size_t)(b*N_)+n0)*C_;

    auto issue=[&](int ch, int st){
        uint32_t base = sb + st*VJ_STAGE;
        int ck0=ch*64;
        for(int i=tid;i<2048;i+=256){
            int r=i>>3, s=i&7;
            size_t gi=(size_t)r*C_ + ck0 + s*8;
            cp16(base+VJ_AH + r*144 + s*16, Ah + gi);
            cp16(base+VJ_AL + r*144 + s*16, Al + gi);
        }
        for(int i=tid;i<512;i+=256){
            int r=i>>3, s=i&7;
            size_t gi=(size_t)(o0+r)*C_ + ck0 + s*8;
            cp16(base+VJ_BH + r*144 + s*16, g_Whh + gi);
            cp16(base+VJ_BL + r*144 + s*16, g_Whl + gi);
        }
    };

    float acc[4][4][4];
    #pragma unroll
    for(int mi=0;mi<4;mi++)
        #pragma unroll
        for(int ni=0;ni<4;ni++)
            #pragma unroll
            for(int e=0;e<4;e++) acc[mi][ni][e]=0.f;

    issue(0,0); CP_COMMIT();
    for(int ch=0; ch<4; ch++){
        if(ch+1<4){ issue(ch+1,(ch+1)&1); CP_COMMIT(); CP_WAIT1(); } else { CP_WAIT0(); }
        __syncthreads();
        uint32_t stg = sb + (ch&1)*VJ_STAGE;
        #pragma unroll
        for(int ks=0;ks<4;ks++){
            int kbo = (ks*16 + lcol*8)*2;
            uint32_t bh[4][2], bl[4][2];
            #pragma unroll
            for(int nb=0;nb<2;nb++){
                uint32_t r4[4];
                uint32_t off = (wk*32+nb*16+lrow)*144 + kbo;
                ldm4(r4, stg+VJ_BH + off);
                bh[2*nb][0]=r4[0]; bh[2*nb+1][0]=r4[1]; bh[2*nb][1]=r4[2]; bh[2*nb+1][1]=r4[3];
                ldm4(r4, stg+VJ_BL + off);
                bl[2*nb][0]=r4[0]; bl[2*nb+1][0]=r4[1]; bl[2*nb][1]=r4[2]; bl[2*nb+1][1]=r4[3];
            }
            #pragma unroll
            for(int mi=0;mi<4;mi++){
                uint32_t ah[4], al[4];
                uint32_t off = (wq*64+mi*16+lrow)*144 + kbo;
                ldm4(ah, stg+VJ_AH + off);
                ldm4(al, stg+VJ_AL + off);
                #pragma unroll
                for(int ni=0;ni<4;ni++){
                    mma16816(acc[mi][ni], ah, bh[ni]);
                    mma16816(acc[mi][ni], ah, bl[ni]);
                    mma16816(acc[mi][ni], al, bh[ni]);
                }
            }
        }
        __syncthreads();
    }
    __half* ep = (__half*)sm;
    #pragma unroll
    for(int mi=0;mi<4;mi++){
        int qr=wq*64+mi*16+g;
        #pragma unroll
        for(int ni=0;ni<4;ni++){
            int oc=wk*32+ni*8+tig*2;
            float2 bia=*(const float2*)&bias[o0+oc];
            ep[(oc+0)*264+qr]   = __float2half_rn(acc[mi][ni][0]+bia.x);
            ep[(oc+1)*264+qr]   = __float2half_rn(acc[mi][ni][1]+bia.y);
            ep[(oc+0)*264+qr+8] = __float2half_rn(acc[mi][ni][2]+bia.x);
            ep[(oc+1)*264+qr+8] = __float2half_rn(acc[mi][ni][3]+bia.y);
        }
    }
    __syncthreads();
    __half* VTo = g_VTh + ((size_t)b*C_ + o0)*N_ + n0;
    for(int e=tid;e<2048;e+=256){
        int r=e>>5, c=(e&31)*8;
        *(uint4*)&VTo[(size_t)r*N_ + c] = *(uint4*)&ep[r*264 + c];
    }
}

// ---------------- sgemm: S = Q K^T, 512 threads, warp 32x64 ----------------
#define SG_Q  0
#define SG_KH 18432
#define SG_STAGE 55296
#define SG_SMEM (3*SG_STAGE)
__global__ __launch_bounds__(512) void sgemm_kernel(){
    extern __shared__ char sm[];
    uint32_t sb = smem_to_u32(sm);
    int tid=threadIdx.x, lane=tid&31, wid=tid>>5;
    int g=lane>>2, tig=lane&3;
    int wq=wid&3, wk=wid>>2;      // 4 q-warps x 4 k-warps; warp = 32q x 64k
    int lrow=lane&15, lcol=lane>>4;
    int b=blockIdx.z, q0=blockIdx.y*128, k0=blockIdx.x*256;
    const __half* Qg=g_Qh+((size_t)b*N_+q0)*CK_;
    const __half* Khg=g_Kh+((size_t)b*N_+k0)*CK_;

    auto issue=[&](int ch, int st){
        uint32_t base = sb + st*SG_STAGE;
        int ck0=ch*64;
        for(int i=tid;i<1024;i+=512){
            int r=i>>3, s=i&7;
            cp16(base+SG_Q + r*144 + s*16, Qg + (size_t)r*CK_ + ck0 + s*8);
        }
        for(int i=tid;i<2048;i+=512){
            int r=i>>3, s=i&7;
            cp16(base+SG_KH + r*144 + s*16, Khg + (size_t)r*CK_ + ck0 + s*8);
        }
    };

    float acc[2][8][4];
    #pragma unroll
    for(int mi=0;mi<2;mi++)
        #pragma unroll
        for(int ni=0;ni<8;ni++)
            #pragma unroll
            for(int e=0;e<4;e++) acc[mi][ni][e]=0.f;

    issue(0,0); CP_COMMIT();
    issue(1,1); CP_COMMIT();
    int st=2;
    for(int ch=0; ch<7; ch++){
        if(ch+2<7){ issue(ch+2,st); CP_COMMIT(); st=(st+1==3)?0:st+1; CP_WAIT2(); }
        else if(ch+1<7){ CP_WAIT1(); }
        else { CP_WAIT0(); }
        __syncthreads();
        uint32_t stg = sb + (ch%3)*SG_STAGE;
        #pragma unroll
        for(int ks=0;ks<4;ks++){
            int kbo = (ks*16 + lcol*8)*2;
            uint32_t bh[8][2];
            #pragma unroll
            for(int nb=0;nb<4;nb++){
                uint32_t r4[4];
                ldm4(r4, stg+SG_KH + (wk*64+nb*16+lrow)*144 + kbo);
                bh[2*nb][0]=r4[0]; bh[2*nb+1][0]=r4[1]; bh[2*nb][1]=r4[2]; bh[2*nb+1][1]=r4[3];
            }
            #pragma unroll
            for(int mi=0;mi<2;mi++){
                uint32_t a[4];
                ldm4(a, stg+SG_Q + (wq*32+mi*16+lrow)*144 + kbo);
                #pragma unroll
                for(int ni=0;ni<8;ni++) mma16816(acc[mi][ni], a, bh[ni]);
            }
        }
        __syncthreads();
    }
    float* So = g_S + ((size_t)b*N_+q0)*N_ + k0;
    #pragma unroll
    for(int mi=0;mi<2;mi++){
        int qr=wq*32+mi*16+g;
        #pragma unroll
        for(int ni=0;ni<8;ni++){
            int kc=wk*64+ni*8+tig*2;
            float2 v0={acc[mi][ni][0],acc[mi][ni][1]};
            float2 v1={acc[mi][ni][2],acc[mi][ni][3]};
            *(float2*)&So[(size_t)qr*N_+kc]     = v0;
            *(float2*)&So[(size_t)(qr+8)*N_+kc] = v1;
        }
    }
}

// ---------------- softmax (additive mask, fp32 S, fp16 P) ----------------
__global__ __launch_bounds__(256) void softmax_kernel(const int* __restrict__ cmask){
    int b=blockIdx.y, q=blockIdx.x, tid=threadIdx.x;
    const float4* Srow=(const float4*)(g_S+((size_t)b*N_+q)*N_);
    const float4* Am=(const float4*)(g_addm + b*N_);
    float cmf = (cmask[b*N_+q]!=0) ? 1.f : 0.f;
    float s[16], mx=-3.4e38f;
    #pragma unroll
    for(int i=0;i<4;i++){
        int k4=tid+i*256;
        float4 v=Srow[k4];
        float4 a=Am[k4];
        v.x=fmaf(cmf,a.x,v.x); v.y=fmaf(cmf,a.y,v.y);
        v.z=fmaf(cmf,a.z,v.z); v.w=fmaf(cmf,a.w,v.w);
        s[4*i]=v.x;s[4*i+1]=v.y;s[4*i+2]=v.z;s[4*i+3]=v.w;
        mx=fmaxf(mx,fmaxf(fmaxf(v.x,v.y),fmaxf(v.z,v.w)));
    }
    #pragma unroll
    for(int o=16;o;o>>=1) mx=fmaxf(mx,__shfl_xor_sync(~0u,mx,o));
    __shared__ float red[8];
    int w=tid>>5,l=tid&31;
    if(l==0) red[w]=mx;
    __syncthreads();
    float M=red[0];
    #pragma unroll
    for(int i=1;i<8;i++) M=fmaxf(M,red[i]);
    __syncthreads();
    float sum=0.f;
    uint2* Prow=(uint2*)(g_P+((size_t)b*N_+q)*N_);
    #pragma unroll
    for(int i=0;i<4;i++){
        __align__(8) __half h[4];
        #pragma unroll
        for(int j=0;j<4;j++){
            float p=fast_exp(s[4*i+j]-M);
            h[j]=__float2half_rn(p);
            sum+=__half2float(h[j]);
        }
        Prow[tid+i*256]=*(uint2*)h;
    }
    #pragma unroll
    for(int o=16;o;o>>=1) sum+=__shfl_xor_sync(~0u,sum,o);
    if(l==0) red[w]=sum;
    __syncthreads();
    if(tid==0){
        float t=0.f;
        #pragma unroll
        for(int i=0;i<8;i++) t+=red[i];
        g_l[b*N_+q]=t;
    }
}

// ---------------- pv: 512 threads, warp 32x32, dual acc, V^2 in-reg ----------------
#define PV_P 0
#define PV_V 18432
#define PV_STAGE 36864
#define PV_SMEM (3*PV_STAGE)
__global__ __launch_bounds__(512) void pv_kernel(){
    extern __shared__ char sm[];
    uint32_t sb = smem_to_u32(sm);
    int tid=threadIdx.x, lane=tid&31, wid=tid>>5;
    int g=lane>>2, tig=lane&3;
    int wq=wid&3, wk=wid>>2;      // 4 q-warps x 4 c-warps; warp = 32q x 32c
    int lrow=lane&15, lcol=lane>>4;
    int b=blockIdx.z, q0=blockIdx.y*128, c0=blockIdx.x*128;
    const __half* Pg = g_P  + ((size_t)b*N_+q0)*N_;
    const __half* Vg = g_VTh+ ((size_t)b*C_+c0)*N_;

    auto issue=[&](int ch, int st){
        uint32_t base = sb + st*PV_STAGE;
        int kk0=ch*64;
        for(int i=tid;i<1024;i+=512){
            int r=i>>3, s=i&7;
            cp16(base+PV_P + r*144 + s*16, Pg + (size_t)r*N_ + kk0 + s*8);
            cp16(base+PV_V + r*144 + s*16, Vg + (size_t)r*N_ + kk0 + s*8);
        }
    };

    float accm[2][4][4], accq[2][4][4];
    #pragma unroll
    for(int mi=0;mi<2;mi++)
        #pragma unroll
        for(int ni=0;ni<4;ni++)
            #pragma unroll
            for(int e=0;e<4;e++){ accm[mi][ni][e]=0.f; accq[mi][ni][e]=0.f; }

    issue(0,0); CP_COMMIT();
    issue(1,1); CP_COMMIT();
    int st=2;
    for(int ch=0; ch<64; ch++){
        if(ch+2<64){ issue(ch+2,st); CP_COMMIT(); st=(st+1==3)?0:st+1; CP_WAIT2(); }
        else if(ch+1<64){ CP_WAIT1(); }
        else { CP_WAIT0(); }
        __syncthreads();
        uint32_t stg = sb + (ch%3)*PV_STAGE;
        #pragma unroll
        for(int ks=0;ks<4;ks++){
            int kbo = (ks*16 + lcol*8)*2;
            uint32_t bh[4][2], bq[4][2];
            #pragma unroll
            for(int nb=0;nb<2;nb++){
                uint32_t r4[4];
                ldm4(r4, stg+PV_V + (wk*32+nb*16+lrow)*144 + kbo);
                bh[2*nb][0]=r4[0]; bh[2*nb+1][0]=r4[1]; bh[2*nb][1]=r4[2]; bh[2*nb+1][1]=r4[3];
            }
            #pragma unroll
            for(int ni=0;ni<4;ni++){
                #pragma unroll
                for(int r=0;r<2;r++){
                    __half2 hv = *(__half2*)&bh[ni][r];
                    __half2 sq = __hmul2(hv, hv);
                    bq[ni][r] = *(uint32_t*)&sq;
                }
            }
            #pragma unroll
            for(int mi=0;mi<2;mi++){
                uint32_t a[4];
                ldm4(a, stg+PV_P + (wq*32+mi*16+lrow)*144 + kbo);
                #pragma unroll
                for(int ni=0;ni<4;ni++){
                    mma16816(accm[mi][ni], a, bh[ni]);
                    mma16816(accq[mi][ni], a, bq[ni]);
                }
            }
        }
        __syncthreads();
    }
    float* Ob = g_O + ((size_t)b*N_+q0)*(2*C_) + 2*c0;
    #pragma unroll
    for(int mi=0;mi<2;mi++){
        int qr=wq*32+mi*16+g;
        #pragma unroll
        for(int ni=0;ni<4;ni++){
            int cc=wk*32+ni*8+tig*2;
            float4 v0={accm[mi][ni][0],accq[mi][ni][0],accm[mi][ni][1],accq[mi][ni][1]};
            float4 v1={accm[mi][ni][2],accq[mi][ni][2],accm[mi][ni][3],accq[mi][ni][3]};
            *(float4*)&Ob[(size_t)qr*(2*C_)+2*cc]     = v0;
            *(float4*)&Ob[(size_t)(qr+8)*(2*C_)+2*cc] = v1;
        }
    }
}

// ---------------- finalize ----------------
__global__ __launch_bounds__(256) void final_kernel(const float* __restrict__ content,
                                                    float* __restrict__ out){
    int b=blockIdx.z, c=blockIdx.y;
    int n=(blockIdx.x*256+threadIdx.x)*4;
    const float* Ob=g_O+(size_t)b*N_*(2*C_);
    float4 l4=*(const float4*)&g_l[b*N_+n];
    float lv[4]={l4.x,l4.y,l4.z,l4.w};
    float cmv=g_cmean[b*C_+c], cr=g_crstd[b*C_+c];
    size_t oi=((size_t)(b*C_+c))*N_+n;
    float4 cx=*(const float4*)&content[oi];
    float ci[4]={cx.x,cx.y,cx.z,cx.w};
    float res[4];
    #pragma unroll
    for(int i=0;i<4;i++){
        float2 mv=*(const float2*)&Ob[(size_t)(n+i)*(2*C_)+2*c];
        float inv=1.0f/lv[i];
        float mean=mv.x*inv, m2=mv.y*inv;
        float sd=sqrtf(fmaxf(m2-mean*mean,0.f));
        res[i]=sd*(ci[i]-cmv)*cr+mean;
    }
    float4 ro={res[0],res[1],res[2],res[3]};
    *(float4*)&out[oi]=ro;
}

// ---------------- launch ----------------
extern "C" void kernel_launch(void* const* d_in, const int* in_sizes, int n_in,
                              void* d_out, int out_size){
    const float* content     = (const float*)d_in[0];
    const float* style       = (const float*)d_in[1];
    const float* content_key = (const float*)d_in[2];
    const float* style_key   = (const float*)d_in[3];
    const int*   cmask       = (const int*)d_in[4];
    const int*   smask       = (const int*)d_in[5];
    const float* Wf=(const float*)d_in[6];  const float* bf=(const float*)d_in[7];
    const float* Wg=(const float*)d_in[8];  const float* bg=(const float*)d_in[9];
    const float* Wh=(const float*)d_in[10]; const float* bh=(const float*)d_in[11];
    float* out=(float*)d_out;

    __half *qh,*kh,*cth,*ctl,*sth,*stl,*wf16,*wg16;
    cudaGetSymbolAddress((void**)&qh,  g_Qh);
    cudaGetSymbolAddress((void**)&kh,  g_Kh);
    cudaGetSymbolAddress((void**)&cth, g_CTh); cudaGetSymbolAddress((void**)&ctl, g_CTl);
    cudaGetSymbolAddress((void**)&sth, g_STh); cudaGetSymbolAddress((void**)&stl, g_STl);
    cudaGetSymbolAddress((void**)&wf16, g_Wf16); cudaGetSymbolAddress((void**)&wg16, g_Wg16);
    cudaFuncSetAttribute(proj_mma_kernel,  cudaFuncAttributeMaxDynamicSharedMemorySize, PJ_SMEM);
    cudaFuncSetAttribute(projv_mma_kernel, cudaFuncAttributeMaxDynamicSharedMemorySize, VJ_SMEM);
    cudaFuncSetAttribute(sgemm_kernel, cudaFuncAttributeMaxDynamicSharedMemorySize, SG_SMEM);
    cudaFuncSetAttribute(pv_kernel,    cudaFuncAttributeMaxDynamicSharedMemorySize, PV_SMEM);

    megaprep_kernel<<<MP_BLOCKS, 256>>>(content, content_key, style_key, style, smask,
                                        Wf, Wg, Wh);
    proj_mma_kernel<<<dim3(7, 16, B_), 256, PJ_SMEM>>>(cth, ctl, wf16, bf, qh);
    proj_mma_kernel<<<dim3(7, 16, B_), 256, PJ_SMEM>>>(sth, stl, wg16, bg, kh);
    sgemm_kernel<<<dim3(16, 32, B_), 512, SG_SMEM>>>();
    projv_mma_kernel<<<dim3(4, 16, B_), 256, VJ_SMEM>>>(bh);
    softmax_kernel<<<dim3(N_, B_), 256>>>(cmask);
    pv_kernel<<<dim3(2, 32, B_), 512, PV_SMEM>>>();
    final_kernel<<<dim3(4, C_, B_), 256>>>(content, out);
}